// round 11
// baseline (speedup 1.0000x reference)
#include <cuda_runtime.h>
#include <cuda_fp16.h>
#include <math.h>
#include <stdint.h>

// ---------------------------------------------------------------------------
// Problem shape (fixed): B=2, S=4096, H=1024, I=3072
// ---------------------------------------------------------------------------
#define M_TOK 8192
#define H_DIM 1024
#define I_DIM 3072

// ---------------------------------------------------------------------------
// Scratch
// ---------------------------------------------------------------------------
__device__ __half g_xh [(size_t)M_TOK * H_DIM];
__device__ __half g_xl [(size_t)M_TOK * H_DIM];
__device__ __half g_wu [(size_t)I_DIM * H_DIM];
__device__ __half g_wg [(size_t)I_DIM * H_DIM];
__device__ __half g_wd [(size_t)H_DIM * I_DIM];
__device__ float g_up  [(size_t)M_TOK * I_DIM];
__device__ float g_gate[(size_t)M_TOK * I_DIM];
__device__ __half g_ph [(size_t)M_TOK * I_DIM];
__device__ __half g_pl [(size_t)M_TOK * I_DIM];
__device__ unsigned int g_amax[8];
// slots: 0=x  1=up_raw  2=gate_raw  3=t  4=p

// ---------------------------------------------------------------------------
// Helpers
// ---------------------------------------------------------------------------
__device__ __forceinline__ float qdq16(float v, float scale) {
    float q = rintf(__fdiv_rn(v, scale));
    q = fminf(fmaxf(q, -32768.0f), 32767.0f);
    return q * scale;
}
__device__ __forceinline__ float scale16(float amax) {
    return fmaxf(__fdiv_rn(amax, 32767.0f), 1e-12f);
}
__device__ __forceinline__ float silu_t(float graw, float sg) {
    float g1 = qdq16(graw, sg);
    float sig = __fdiv_rn(1.0f, 1.0f + expf(-g1));
    sig = fminf(fmaxf(rintf(sig * 65536.0f), 0.0f), 65535.0f) * (1.0f / 65536.0f);
    return g1 * sig;
}
__device__ __forceinline__ uint32_t smem_u32(const void* p) {
    uint32_t a;
    asm("{ .reg .u64 t; cvta.to.shared.u64 t, %1; cvt.u32.u64 %0, t; }"
        : "=r"(a) : "l"(p));
    return a;
}
__device__ __forceinline__ void cp16(uint32_t dst, const void* src) {
    asm volatile("cp.async.cg.shared.global [%0], [%1], 16;"
                 :: "r"(dst), "l"(src) : "memory");
}
__device__ __forceinline__ void ldsm_x4(uint32_t addr, uint32_t* r) {
    asm volatile("ldmatrix.sync.aligned.m8n8.x4.shared.b16 {%0,%1,%2,%3}, [%4];"
                 : "=r"(r[0]), "=r"(r[1]), "=r"(r[2]), "=r"(r[3]) : "r"(addr));
}
__device__ __forceinline__ void mma16816(float* c, const uint32_t* a,
                                         uint32_t b0, uint32_t b1) {
    asm volatile(
        "mma.sync.aligned.m16n8k16.row.col.f32.f16.f16.f32 "
        "{%0,%1,%2,%3}, {%4,%5,%6,%7}, {%8,%9}, {%0,%1,%2,%3};"
        : "+f"(c[0]), "+f"(c[1]), "+f"(c[2]), "+f"(c[3])
        : "r"(a[0]), "r"(a[1]), "r"(a[2]), "r"(a[3]), "r"(b0), "r"(b1));
}

// ---------------------------------------------------------------------------
// GEMM: C[M,N] = (Ah+Al)[M,K] @ Wh[N,K]^T      (fp16, fp32 accumulate)
// 128x256 CTA tile, 512 threads (4m x 4n warps, warp tile 32x64),
// K-chunk 64, SW128-swizzled smem, 3-stage cp.async pipeline (64KB/stage).
// Rationale: BN=256 cuts A-side LTS traffic ~2x (the measured bottleneck).
// ---------------------------------------------------------------------------
#define BMT 128
#define BNT 256
#define NSTAGES 3
#define A_TILE 16384                         // 128 rows x 128B (per split half)
#define B_OFF  (2 * A_TILE)                  // 32768
#define B_TILE 32768                         // 256 rows x 128B
#define STAGE_BYTES (B_OFF + B_TILE)         // 65536
#define GEMM_DYN_SMEM (NSTAGES * STAGE_BYTES + 1024)

__device__ __forceinline__ void load_chunk(
    uint32_t sbase,
    const __half* __restrict__ Ah, const __half* __restrict__ Al,
    const __half* __restrict__ Bh,
    int m0, int n0, int K, int k0, int tid)
{
    // A: 128 rows x 128B, both halves (2 iters/thread)
    #pragma unroll
    for (int u = tid; u < 1024; u += 512) {
        int r = u >> 3, cc = u & 7;
        uint32_t off = (uint32_t)(r * 128 + cc * 16);
        uint32_t sw = off ^ ((off >> 3) & 0x70);
        size_t arow = (size_t)(m0 + r) * K + k0 + cc * 8;
        cp16(sbase + sw,          Ah + arow);
        cp16(sbase + A_TILE + sw, Al + arow);
    }
    // B: 256 rows x 128B (4 iters/thread)
    #pragma unroll
    for (int u = tid; u < 2048; u += 512) {
        int r = u >> 3, cc = u & 7;
        uint32_t off = (uint32_t)(r * 128 + cc * 16);
        uint32_t sw = off ^ ((off >> 3) & 0x70);
        size_t brow = (size_t)(n0 + r) * K + k0 + cc * 8;
        cp16(sbase + B_OFF + sw, Bh + brow);
    }
}

__global__ void __launch_bounds__(512, 1)
gemm_fp16_split(const __half* __restrict__ Ah, const __half* __restrict__ Al,
                const __half* __restrict__ Bh,
                float* __restrict__ C, int N, int K, unsigned int* amax_slot)
{
    extern __shared__ char dynsmem[];
    __shared__ float s_red[16];
    const int tid = threadIdx.x;
    const int wid = tid >> 5;
    const int lid = tid & 31;
    const int m0 = blockIdx.y * BMT;
    const int n0 = blockIdx.x * BNT;
    const int NC = K >> 6;
    uint32_t dynbase = smem_u32(dynsmem);
    dynbase = (dynbase + 1023u) & ~1023u;

    // warp grid: 4 (m) x 4 (n); warp tile 32x64
    const int m0w = (wid & 3) * 32;
    const int n0w = (wid >> 2) * 64;
    float acc[2][8][4];
    #pragma unroll
    for (int i = 0; i < 2; i++)
        #pragma unroll
        for (int j = 0; j < 8; j++)
            #pragma unroll
            for (int q = 0; q < 4; q++) acc[i][j][q] = 0.0f;

    const int g  = lid >> 3;
    const int lr = lid & 7;
    const int rsel = (g & 1) * 8 + lr;
    const int csel = (g >> 1) * 16;

    #pragma unroll
    for (int c = 0; c < NSTAGES; c++) {
        load_chunk(dynbase + c * STAGE_BYTES, Ah, Al, Bh, m0, n0, K, c * 64, tid);
        asm volatile("cp.async.commit_group;" ::: "memory");
    }

    for (int c = 0; c < NC; ++c) {
        int s = c - (c / NSTAGES) * NSTAGES;
        asm volatile("cp.async.wait_group %0;" :: "n"(NSTAGES - 1) : "memory");
        __syncthreads();
        uint32_t sb = dynbase + s * STAGE_BYTES;
        uint32_t aH = sb, aL = sb + A_TILE;
        uint32_t bH = sb + B_OFF;

        #pragma unroll
        for (int ks = 0; ks < 4; ks++) {
            const int cb = ks * 32 + csel;
            uint32_t ah[2][4], al[2][4];
            #pragma unroll
            for (int mt = 0; mt < 2; mt++) {
                uint32_t off = (uint32_t)((m0w + mt * 16 + rsel) * 128 + cb);
                uint32_t sw = off ^ ((off >> 3) & 0x70);
                ldsm_x4(aH + sw, ah[mt]);
                ldsm_x4(aL + sw, al[mt]);
            }
            #pragma unroll
            for (int np = 0; np < 4; np++) {
                uint32_t off = (uint32_t)((n0w + np * 16 + rsel) * 128 + cb);
                uint32_t sw = off ^ ((off >> 3) & 0x70);
                uint32_t bh[4];
                ldsm_x4(bH + sw, bh);
                #pragma unroll
                for (int mt = 0; mt < 2; mt++) {
                    mma16816(acc[mt][np * 2 + 0], ah[mt], bh[0], bh[2]);
                    mma16816(acc[mt][np * 2 + 1], ah[mt], bh[1], bh[3]);
                    mma16816(acc[mt][np * 2 + 0], al[mt], bh[0], bh[2]);
                    mma16816(acc[mt][np * 2 + 1], al[mt], bh[1], bh[3]);
                }
            }
        }
        __syncthreads();
        if (c + NSTAGES < NC) {
            load_chunk(dynbase + s * STAGE_BYTES, Ah, Al, Bh, m0, n0, K,
                       (c + NSTAGES) * 64, tid);
        }
        asm volatile("cp.async.commit_group;" ::: "memory");
    }

    // epilogue
    const int gq = lid >> 2, q4 = lid & 3;
    float lmax = 0.0f;
    #pragma unroll
    for (int mt = 0; mt < 2; mt++) {
        #pragma unroll
        for (int nt = 0; nt < 8; nt++) {
            float* cp0 = C + (size_t)(m0 + m0w + mt * 16 + gq) * N
                           + n0 + n0w + nt * 8 + q4 * 2;
            float* cp1 = cp0 + 8 * (size_t)N;
            cp0[0] = acc[mt][nt][0]; cp0[1] = acc[mt][nt][1];
            cp1[0] = acc[mt][nt][2]; cp1[1] = acc[mt][nt][3];
            #pragma unroll
            for (int q = 0; q < 4; q++)
                lmax = fmaxf(lmax, fabsf(acc[mt][nt][q]));
        }
    }
    if (amax_slot) {
        #pragma unroll
        for (int o = 16; o; o >>= 1)
            lmax = fmaxf(lmax, __shfl_xor_sync(0xffffffffu, lmax, o));
        if (lid == 0) s_red[wid] = lmax;
        __syncthreads();
        if (tid == 0) {
            float m = s_red[0];
            #pragma unroll
            for (int i = 1; i < 16; i++) m = fmaxf(m, s_red[i]);
            atomicMax(amax_slot, __float_as_uint(m));
        }
    }
}

// ---------------------------------------------------------------------------
// Elementwise
// ---------------------------------------------------------------------------
__global__ void k_zero_amax() {
    if (threadIdx.x < 8) g_amax[threadIdx.x] = 0u;
}

__global__ void k_amax(const float4* __restrict__ p, size_t n4, int slot) {
    float m = 0.0f;
    for (size_t i = (size_t)blockIdx.x * blockDim.x + threadIdx.x; i < n4;
         i += (size_t)gridDim.x * blockDim.x) {
        float4 v = p[i];
        m = fmaxf(m, fmaxf(fmaxf(fabsf(v.x), fabsf(v.y)),
                           fmaxf(fabsf(v.z), fabsf(v.w))));
    }
    #pragma unroll
    for (int o = 16; o; o >>= 1) m = fmaxf(m, __shfl_xor_sync(0xffffffffu, m, o));
    __shared__ float red[32];
    int wid = threadIdx.x >> 5, lid = threadIdx.x & 31;
    if (lid == 0) red[wid] = m;
    __syncthreads();
    if (threadIdx.x == 0) {
        int nw = (blockDim.x + 31) >> 5;
        float mm = red[0];
        for (int i = 1; i < nw; i++) mm = fmaxf(mm, red[i]);
        atomicMax(&g_amax[slot], __float_as_uint(mm));
    }
}

// qdq16 then fp16 hi/lo split (near-exact for 16-bit grid values)
__global__ void k_quant_split(const float4* __restrict__ in,
                              __half2* __restrict__ h,
                              __half2* __restrict__ l,
                              size_t n4, int slot) {
    float s = scale16(__uint_as_float(g_amax[slot]));
    for (size_t i = (size_t)blockIdx.x * blockDim.x + threadIdx.x; i < n4;
         i += (size_t)gridDim.x * blockDim.x) {
        float4 v = in[i];
        float q[4] = {qdq16(v.x, s), qdq16(v.y, s), qdq16(v.z, s), qdq16(v.w, s)};
        __half hh[4], ll[4];
        #pragma unroll
        for (int c = 0; c < 4; c++) {
            hh[c] = __float2half_rn(q[c]);
            ll[c] = __float2half_rn(q[c] - __half2float(hh[c]));
        }
        h[2 * i]     = __halves2half2(hh[0], hh[1]);
        h[2 * i + 1] = __halves2half2(hh[2], hh[3]);
        l[2 * i]     = __halves2half2(ll[0], ll[1]);
        l[2 * i + 1] = __halves2half2(ll[2], ll[3]);
    }
}

// blockwise 4-bit weight fake qdq -> single fp16 (vectorized: 4 elems/thread)
__global__ void k_dequant_w(const float4* __restrict__ w,
                            __half2* __restrict__ oh, int n4) {
    int i = blockIdx.x * blockDim.x + threadIdx.x;
    if (i >= n4) return;
    float4 v = w[i];
    float r[4] = {v.x, v.y, v.z, v.w};
    float a = fmaxf(fmaxf(fabsf(r[0]), fabsf(r[1])),
                    fmaxf(fabsf(r[2]), fabsf(r[3])));
    #pragma unroll
    for (int o = 1; o < 8; o <<= 1)
        a = fmaxf(a, __shfl_xor_sync(0xffffffffu, a, o));
    float s = fmaxf(__fdiv_rn(a, 7.0f), 1e-12f);
    __half hh[4];
    #pragma unroll
    for (int c = 0; c < 4; c++) {
        float q = rintf(__fdiv_rn(r[c], s));
        q = fminf(fmaxf(q, -8.0f), 7.0f);
        hh[c] = __float2half_rn(q * s);
    }
    oh[2 * i]     = __halves2half2(hh[0], hh[1]);
    oh[2 * i + 1] = __halves2half2(hh[2], hh[3]);
}

// Pass 1: amax(t) from gate_raw
__global__ void k_amax_t(const float4* __restrict__ gate, size_t n4) {
    float sg = scale16(__uint_as_float(g_amax[2]));
    float m = 0.0f;
    for (size_t i = (size_t)blockIdx.x * blockDim.x + threadIdx.x; i < n4;
         i += (size_t)gridDim.x * blockDim.x) {
        float4 v = gate[i];
        m = fmaxf(m, fabsf(silu_t(v.x, sg)));
        m = fmaxf(m, fabsf(silu_t(v.y, sg)));
        m = fmaxf(m, fabsf(silu_t(v.z, sg)));
        m = fmaxf(m, fabsf(silu_t(v.w, sg)));
    }
    #pragma unroll
    for (int o = 16; o; o >>= 1) m = fmaxf(m, __shfl_xor_sync(0xffffffffu, m, o));
    __shared__ float red[32];
    int wid = threadIdx.x >> 5, lid = threadIdx.x & 31;
    if (lid == 0) red[wid] = m;
    __syncthreads();
    if (threadIdx.x == 0) {
        int nw = (blockDim.x + 31) >> 5;
        float mm = red[0];
        for (int i = 1; i < nw; i++) mm = fmaxf(mm, red[i]);
        atomicMax(&g_amax[3], __float_as_uint(mm));
    }
}

// Pass 2: amax(p) (recompute t)
__global__ void k_amax_p(const float4* __restrict__ gate,
                         const float4* __restrict__ up, size_t n4) {
    float sg = scale16(__uint_as_float(g_amax[2]));
    float st = scale16(__uint_as_float(g_amax[3]));
    float su = scale16(__uint_as_float(g_amax[1]));
    float m = 0.0f;
    for (size_t i = (size_t)blockIdx.x * blockDim.x + threadIdx.x; i < n4;
         i += (size_t)gridDim.x * blockDim.x) {
        float4 gv = gate[i];
        float4 uv = up[i];
        float rg[4] = {gv.x, gv.y, gv.z, gv.w};
        float ru[4] = {uv.x, uv.y, uv.z, uv.w};
        #pragma unroll
        for (int c = 0; c < 4; c++) {
            float g2 = qdq16(silu_t(rg[c], sg), st);
            float u  = qdq16(ru[c], su);
            m = fmaxf(m, fabsf(g2 * u));
        }
    }
    #pragma unroll
    for (int o = 16; o; o >>= 1) m = fmaxf(m, __shfl_xor_sync(0xffffffffu, m, o));
    __shared__ float red[32];
    int wid = threadIdx.x >> 5, lid = threadIdx.x & 31;
    if (lid == 0) red[wid] = m;
    __syncthreads();
    if (threadIdx.x == 0) {
        int nw = (blockDim.x + 31) >> 5;
        float mm = red[0];
        for (int i = 1; i < nw; i++) mm = fmaxf(mm, red[i]);
        atomicMax(&g_amax[4], __float_as_uint(mm));
    }
}

// Pass 3: recompute p, qdq final, split-write fp16 ph/pl
__global__ void k_write_p(const float4* __restrict__ gate,
                          const float4* __restrict__ up,
                          __half2* __restrict__ ph,
                          __half2* __restrict__ pl, size_t n4) {
    float sg = scale16(__uint_as_float(g_amax[2]));
    float st = scale16(__uint_as_float(g_amax[3]));
    float su = scale16(__uint_as_float(g_amax[1]));
    float sp = scale16(__uint_as_float(g_amax[4]));
    for (size_t i = (size_t)blockIdx.x * blockDim.x + threadIdx.x; i < n4;
         i += (size_t)gridDim.x * blockDim.x) {
        float4 gv = gate[i];
        float4 uv = up[i];
        float rg[4] = {gv.x, gv.y, gv.z, gv.w};
        float ru[4] = {uv.x, uv.y, uv.z, uv.w};
        __half hh[4], ll[4];
        #pragma unroll
        for (int c = 0; c < 4; c++) {
            float g2 = qdq16(silu_t(rg[c], sg), st);
            float u  = qdq16(ru[c], su);
            float o  = qdq16(g2 * u, sp);
            hh[c] = __float2half_rn(o);
            ll[c] = __float2half_rn(o - __half2float(hh[c]));
        }
        ph[2 * i]     = __halves2half2(hh[0], hh[1]);
        ph[2 * i + 1] = __halves2half2(hh[2], hh[3]);
        pl[2 * i]     = __halves2half2(ll[0], ll[1]);
        pl[2 * i + 1] = __halves2half2(ll[2], ll[3]);
    }
}

// ---------------------------------------------------------------------------
// Host launch
// ---------------------------------------------------------------------------
extern "C" void kernel_launch(void* const* d_in, const int* in_sizes, int n_in,
                              void* d_out, int out_size)
{
    const float* x  = (const float*)d_in[0];
    const float* wg = (const float*)d_in[1];
    const float* wu = (const float*)d_in[2];
    const float* wd = (const float*)d_in[3];
    float* out = (float*)d_out;

    __half *p_xh, *p_xl, *p_wu, *p_wg, *p_wd, *p_ph, *p_pl;
    float *p_up, *p_gate;
    unsigned int* p_amax;
    cudaGetSymbolAddress((void**)&p_xh,  g_xh);
    cudaGetSymbolAddress((void**)&p_xl,  g_xl);
    cudaGetSymbolAddress((void**)&p_wu,  g_wu);
    cudaGetSymbolAddress((void**)&p_wg,  g_wg);
    cudaGetSymbolAddress((void**)&p_wd,  g_wd);
    cudaGetSymbolAddress((void**)&p_ph,  g_ph);
    cudaGetSymbolAddress((void**)&p_pl,  g_pl);
    cudaGetSymbolAddress((void**)&p_up,  g_up);
    cudaGetSymbolAddress((void**)&p_gate, g_gate);
    cudaGetSymbolAddress((void**)&p_amax, g_amax);

    cudaFuncSetAttribute(gemm_fp16_split,
                         cudaFuncAttributeMaxDynamicSharedMemorySize, GEMM_DYN_SMEM);

    const size_t nx4 = (size_t)M_TOK * H_DIM / 4;
    const size_t ni4 = (size_t)M_TOK * I_DIM / 4;
    const int nw4 = (I_DIM * H_DIM) / 4;

    k_zero_amax<<<1, 8>>>();
    k_amax<<<2048, 256>>>((const float4*)x, nx4, 0);
    k_quant_split<<<2048, 256>>>((const float4*)x, (__half2*)p_xh,
                                 (__half2*)p_xl, nx4, 0);
    k_dequant_w<<<nw4 / 256, 256>>>((const float4*)wu, (__half2*)p_wu, nw4);
    k_dequant_w<<<nw4 / 256, 256>>>((const float4*)wg, (__half2*)p_wg, nw4);

    // up GEMM
    {
        dim3 grid(I_DIM / BNT, M_TOK / BMT);     // (12, 64)
        gemm_fp16_split<<<grid, 512, GEMM_DYN_SMEM>>>(
            p_xh, p_xl, p_wu, p_up, I_DIM, H_DIM, p_amax + 1);
    }
    // gate GEMM
    {
        dim3 grid(I_DIM / BNT, M_TOK / BMT);
        gemm_fp16_split<<<grid, 512, GEMM_DYN_SMEM>>>(
            p_xh, p_xl, p_wg, p_gate, I_DIM, H_DIM, p_amax + 2);
    }
    k_dequant_w<<<nw4 / 256, 256>>>((const float4*)wd, (__half2*)p_wd, nw4);

    // SiLU chain (recompute; no t/p materialization)
    k_amax_t<<<4096, 256>>>((const float4*)p_gate, ni4);
    k_amax_p<<<4096, 256>>>((const float4*)p_gate, (const float4*)p_up, ni4);
    k_write_p<<<4096, 256>>>((const float4*)p_gate, (const float4*)p_up,
                             (__half2*)p_ph, (__half2*)p_pl, ni4);

    // down GEMM
    {
        dim3 grid(H_DIM / BNT, M_TOK / BMT);     // (4, 64)
        gemm_fp16_split<<<grid, 512, GEMM_DYN_SMEM>>>(
            p_ph, p_pl, p_wd, out, H_DIM, I_DIM, nullptr);
    }
}

// round 12
// speedup vs baseline: 1.1392x; 1.1392x over previous
#include <cuda_runtime.h>
#include <cuda_fp16.h>
#include <math.h>
#include <stdint.h>

// ---------------------------------------------------------------------------
// Problem shape (fixed): B=2, S=4096, H=1024, I=3072
// ---------------------------------------------------------------------------
#define M_TOK 8192
#define H_DIM 1024
#define I_DIM 3072

// ---------------------------------------------------------------------------
// Scratch
// ---------------------------------------------------------------------------
__device__ __half g_xh [(size_t)M_TOK * H_DIM];
__device__ __half g_xl [(size_t)M_TOK * H_DIM];
__device__ __half g_wu [(size_t)I_DIM * H_DIM];
__device__ __half g_wg [(size_t)I_DIM * H_DIM];
__device__ __half g_wd [(size_t)H_DIM * I_DIM];
__device__ float g_up  [(size_t)M_TOK * I_DIM];
__device__ float g_gate[(size_t)M_TOK * I_DIM];
__device__ __half g_ph [(size_t)M_TOK * I_DIM];
__device__ __half g_pl [(size_t)M_TOK * I_DIM];
__device__ unsigned int g_amax[8];
// slots: 0=x  1=up_raw  2=gate_raw  3=t  4=p

// ---------------------------------------------------------------------------
// Helpers
// ---------------------------------------------------------------------------
__device__ __forceinline__ float qdq16(float v, float scale) {
    float q = rintf(__fdiv_rn(v, scale));
    q = fminf(fmaxf(q, -32768.0f), 32767.0f);
    return q * scale;
}
__device__ __forceinline__ float scale16(float amax) {
    return fmaxf(__fdiv_rn(amax, 32767.0f), 1e-12f);
}
__device__ __forceinline__ float silu_t(float graw, float sg) {
    float g1 = qdq16(graw, sg);
    float sig = __fdiv_rn(1.0f, 1.0f + expf(-g1));
    sig = fminf(fmaxf(rintf(sig * 65536.0f), 0.0f), 65535.0f) * (1.0f / 65536.0f);
    return g1 * sig;
}
__device__ __forceinline__ uint32_t smem_u32(const void* p) {
    uint32_t a;
    asm("{ .reg .u64 t; cvta.to.shared.u64 t, %1; cvt.u32.u64 %0, t; }"
        : "=r"(a) : "l"(p));
    return a;
}
__device__ __forceinline__ void cp16(uint32_t dst, const void* src) {
    asm volatile("cp.async.cg.shared.global [%0], [%1], 16;"
                 :: "r"(dst), "l"(src) : "memory");
}
__device__ __forceinline__ void ldsm_x4(uint32_t addr, uint32_t* r) {
    asm volatile("ldmatrix.sync.aligned.m8n8.x4.shared.b16 {%0,%1,%2,%3}, [%4];"
                 : "=r"(r[0]), "=r"(r[1]), "=r"(r[2]), "=r"(r[3]) : "r"(addr));
}
__device__ __forceinline__ void mma16816(float* c, const uint32_t* a,
                                         uint32_t b0, uint32_t b1) {
    asm volatile(
        "mma.sync.aligned.m16n8k16.row.col.f32.f16.f16.f32 "
        "{%0,%1,%2,%3}, {%4,%5,%6,%7}, {%8,%9}, {%0,%1,%2,%3};"
        : "+f"(c[0]), "+f"(c[1]), "+f"(c[2]), "+f"(c[3])
        : "r"(a[0]), "r"(a[1]), "r"(a[2]), "r"(a[3]), "r"(b0), "r"(b1));
}

// ---------------------------------------------------------------------------
// GEMM: C[M,N] = (Ah+Al)[M,K] @ Wh[N,K]^T      (fp16, fp32 accumulate)
// 128x128 CTA tile, 128 threads = 4 warps, warp tile 64x64 (2m x 2n grid).
// K-chunk 64, SW128-swizzled smem, 2-stage pipeline, 96KB -> 2 CTAs/SM.
// Rationale vs R10: fatter warp tiles cut LDSM smem reads 128->96 KB/chunk
// (the crossbar is the measured binding constraint); HMMA count unchanged.
// ---------------------------------------------------------------------------
#define NSTAGES 2
#define TILE_BYTES 16384
#define STAGE_BYTES (3 * TILE_BYTES)               // Ah, Al, Wh
#define GEMM_DYN_SMEM (NSTAGES * STAGE_BYTES + 1024)
#define GTHREADS 128

__device__ __forceinline__ void load_chunk(
    uint32_t sbase,
    const __half* __restrict__ Ah, const __half* __restrict__ Al,
    const __half* __restrict__ Bh,
    int m0, int n0, int K, int k0, int tid)
{
    #pragma unroll
    for (int u = tid; u < 1024; u += GTHREADS) {
        int r = u >> 3, cc = u & 7;
        uint32_t off = (uint32_t)(r * 128 + cc * 16);
        uint32_t sw = off ^ ((off >> 3) & 0x70);
        size_t arow = (size_t)(m0 + r) * K + k0 + cc * 8;
        size_t brow = (size_t)(n0 + r) * K + k0 + cc * 8;
        cp16(sbase + sw,                  Ah + arow);
        cp16(sbase + TILE_BYTES + sw,     Al + arow);
        cp16(sbase + 2 * TILE_BYTES + sw, Bh + brow);
    }
}

__global__ void __launch_bounds__(GTHREADS, 2)
gemm_fp16_split(const __half* __restrict__ Ah, const __half* __restrict__ Al,
                const __half* __restrict__ Bh,
                float* __restrict__ C, int N, int K, unsigned int* amax_slot)
{
    extern __shared__ char dynsmem[];
    __shared__ float s_red[4];
    const int tid = threadIdx.x;
    const int wid = tid >> 5;
    const int lid = tid & 31;
    const int m0 = blockIdx.y * 128;
    const int n0 = blockIdx.x * 128;
    const int NC = K >> 6;
    uint32_t dynbase = smem_u32(dynsmem);
    dynbase = (dynbase + 1023u) & ~1023u;

    // warp grid: 2 (m) x 2 (n); warp tile 64x64
    const int m0w = (wid & 1) * 64;
    const int n0w = (wid >> 1) * 64;
    float acc[4][8][4];
    #pragma unroll
    for (int i = 0; i < 4; i++)
        #pragma unroll
        for (int j = 0; j < 8; j++)
            #pragma unroll
            for (int q = 0; q < 4; q++) acc[i][j][q] = 0.0f;

    const int g  = lid >> 3;
    const int lr = lid & 7;
    const int rsel = (g & 1) * 8 + lr;
    const int csel = (g >> 1) * 16;

    #pragma unroll
    for (int c = 0; c < NSTAGES; c++) {
        load_chunk(dynbase + c * STAGE_BYTES, Ah, Al, Bh, m0, n0, K, c * 64, tid);
        asm volatile("cp.async.commit_group;" ::: "memory");
    }

    for (int c = 0; c < NC; ++c) {
        int s = c & (NSTAGES - 1);
        asm volatile("cp.async.wait_group %0;" :: "n"(NSTAGES - 1) : "memory");
        __syncthreads();
        uint32_t sb = dynbase + s * STAGE_BYTES;
        uint32_t aH = sb, aL = sb + TILE_BYTES;
        uint32_t bH = sb + 2 * TILE_BYTES;

        #pragma unroll
        for (int ks = 0; ks < 4; ks++) {
            const int cb = ks * 32 + csel;
            uint32_t ah[4][4], al[4][4];
            #pragma unroll
            for (int mt = 0; mt < 4; mt++) {
                uint32_t off = (uint32_t)((m0w + mt * 16 + rsel) * 128 + cb);
                uint32_t sw = off ^ ((off >> 3) & 0x70);
                ldsm_x4(aH + sw, ah[mt]);
                ldsm_x4(aL + sw, al[mt]);
            }
            #pragma unroll
            for (int np = 0; np < 4; np++) {
                uint32_t off = (uint32_t)((n0w + np * 16 + rsel) * 128 + cb);
                uint32_t sw = off ^ ((off >> 3) & 0x70);
                uint32_t bh[4];
                ldsm_x4(bH + sw, bh);
                #pragma unroll
                for (int mt = 0; mt < 4; mt++) {
                    mma16816(acc[mt][np * 2 + 0], ah[mt], bh[0], bh[2]);
                    mma16816(acc[mt][np * 2 + 1], ah[mt], bh[1], bh[3]);
                    mma16816(acc[mt][np * 2 + 0], al[mt], bh[0], bh[2]);
                    mma16816(acc[mt][np * 2 + 1], al[mt], bh[1], bh[3]);
                }
            }
        }
        __syncthreads();
        if (c + NSTAGES < NC) {
            load_chunk(dynbase + s * STAGE_BYTES, Ah, Al, Bh, m0, n0, K,
                       (c + NSTAGES) * 64, tid);
        }
        asm volatile("cp.async.commit_group;" ::: "memory");
    }

    // epilogue
    const int gq = lid >> 2, q4 = lid & 3;
    float lmax = 0.0f;
    #pragma unroll
    for (int mt = 0; mt < 4; mt++) {
        #pragma unroll
        for (int nt = 0; nt < 8; nt++) {
            float* cp0 = C + (size_t)(m0 + m0w + mt * 16 + gq) * N
                           + n0 + n0w + nt * 8 + q4 * 2;
            float* cp1 = cp0 + 8 * (size_t)N;
            cp0[0] = acc[mt][nt][0]; cp0[1] = acc[mt][nt][1];
            cp1[0] = acc[mt][nt][2]; cp1[1] = acc[mt][nt][3];
            #pragma unroll
            for (int q = 0; q < 4; q++)
                lmax = fmaxf(lmax, fabsf(acc[mt][nt][q]));
        }
    }
    if (amax_slot) {
        #pragma unroll
        for (int o = 16; o; o >>= 1)
            lmax = fmaxf(lmax, __shfl_xor_sync(0xffffffffu, lmax, o));
        if (lid == 0) s_red[wid] = lmax;
        __syncthreads();
        if (tid == 0) {
            float m = s_red[0];
            #pragma unroll
            for (int i = 1; i < 4; i++) m = fmaxf(m, s_red[i]);
            atomicMax(amax_slot, __float_as_uint(m));
        }
    }
}

// ---------------------------------------------------------------------------
// Elementwise
// ---------------------------------------------------------------------------
__global__ void k_zero_amax() {
    if (threadIdx.x < 8) g_amax[threadIdx.x] = 0u;
}

__global__ void k_amax(const float4* __restrict__ p, size_t n4, int slot) {
    float m = 0.0f;
    for (size_t i = (size_t)blockIdx.x * blockDim.x + threadIdx.x; i < n4;
         i += (size_t)gridDim.x * blockDim.x) {
        float4 v = p[i];
        m = fmaxf(m, fmaxf(fmaxf(fabsf(v.x), fabsf(v.y)),
                           fmaxf(fabsf(v.z), fabsf(v.w))));
    }
    #pragma unroll
    for (int o = 16; o; o >>= 1) m = fmaxf(m, __shfl_xor_sync(0xffffffffu, m, o));
    __shared__ float red[32];
    int wid = threadIdx.x >> 5, lid = threadIdx.x & 31;
    if (lid == 0) red[wid] = m;
    __syncthreads();
    if (threadIdx.x == 0) {
        int nw = (blockDim.x + 31) >> 5;
        float mm = red[0];
        for (int i = 1; i < nw; i++) mm = fmaxf(mm, red[i]);
        atomicMax(&g_amax[slot], __float_as_uint(mm));
    }
}

// qdq16 then fp16 hi/lo split (near-exact for 16-bit grid values)
__global__ void k_quant_split(const float4* __restrict__ in,
                              __half2* __restrict__ h,
                              __half2* __restrict__ l,
                              size_t n4, int slot) {
    float s = scale16(__uint_as_float(g_amax[slot]));
    for (size_t i = (size_t)blockIdx.x * blockDim.x + threadIdx.x; i < n4;
         i += (size_t)gridDim.x * blockDim.x) {
        float4 v = in[i];
        float q[4] = {qdq16(v.x, s), qdq16(v.y, s), qdq16(v.z, s), qdq16(v.w, s)};
        __half hh[4], ll[4];
        #pragma unroll
        for (int c = 0; c < 4; c++) {
            hh[c] = __float2half_rn(q[c]);
            ll[c] = __float2half_rn(q[c] - __half2float(hh[c]));
        }
        h[2 * i]     = __halves2half2(hh[0], hh[1]);
        h[2 * i + 1] = __halves2half2(hh[2], hh[3]);
        l[2 * i]     = __halves2half2(ll[0], ll[1]);
        l[2 * i + 1] = __halves2half2(ll[2], ll[3]);
    }
}

// blockwise 4-bit weight fake qdq -> single fp16 (vectorized: 4 elems/thread)
__global__ void k_dequant_w(const float4* __restrict__ w,
                            __half2* __restrict__ oh, int n4) {
    int i = blockIdx.x * blockDim.x + threadIdx.x;
    if (i >= n4) return;
    float4 v = w[i];
    float r[4] = {v.x, v.y, v.z, v.w};
    float a = fmaxf(fmaxf(fabsf(r[0]), fabsf(r[1])),
                    fmaxf(fabsf(r[2]), fabsf(r[3])));
    #pragma unroll
    for (int o = 1; o < 8; o <<= 1)
        a = fmaxf(a, __shfl_xor_sync(0xffffffffu, a, o));
    float s = fmaxf(__fdiv_rn(a, 7.0f), 1e-12f);
    __half hh[4];
    #pragma unroll
    for (int c = 0; c < 4; c++) {
        float q = rintf(__fdiv_rn(r[c], s));
        q = fminf(fmaxf(q, -8.0f), 7.0f);
        hh[c] = __float2half_rn(q * s);
    }
    oh[2 * i]     = __halves2half2(hh[0], hh[1]);
    oh[2 * i + 1] = __halves2half2(hh[2], hh[3]);
}

// Pass 1: amax(t) from gate_raw
__global__ void k_amax_t(const float4* __restrict__ gate, size_t n4) {
    float sg = scale16(__uint_as_float(g_amax[2]));
    float m = 0.0f;
    for (size_t i = (size_t)blockIdx.x * blockDim.x + threadIdx.x; i < n4;
         i += (size_t)gridDim.x * blockDim.x) {
        float4 v = gate[i];
        m = fmaxf(m, fabsf(silu_t(v.x, sg)));
        m = fmaxf(m, fabsf(silu_t(v.y, sg)));
        m = fmaxf(m, fabsf(silu_t(v.z, sg)));
        m = fmaxf(m, fabsf(silu_t(v.w, sg)));
    }
    #pragma unroll
    for (int o = 16; o; o >>= 1) m = fmaxf(m, __shfl_xor_sync(0xffffffffu, m, o));
    __shared__ float red[32];
    int wid = threadIdx.x >> 5, lid = threadIdx.x & 31;
    if (lid == 0) red[wid] = m;
    __syncthreads();
    if (threadIdx.x == 0) {
        int nw = (blockDim.x + 31) >> 5;
        float mm = red[0];
        for (int i = 1; i < nw; i++) mm = fmaxf(mm, red[i]);
        atomicMax(&g_amax[3], __float_as_uint(mm));
    }
}

// Pass 2: amax(p) (recompute t)
__global__ void k_amax_p(const float4* __restrict__ gate,
                         const float4* __restrict__ up, size_t n4) {
    float sg = scale16(__uint_as_float(g_amax[2]));
    float st = scale16(__uint_as_float(g_amax[3]));
    float su = scale16(__uint_as_float(g_amax[1]));
    float m = 0.0f;
    for (size_t i = (size_t)blockIdx.x * blockDim.x + threadIdx.x; i < n4;
         i += (size_t)gridDim.x * blockDim.x) {
        float4 gv = gate[i];
        float4 uv = up[i];
        float rg[4] = {gv.x, gv.y, gv.z, gv.w};
        float ru[4] = {uv.x, uv.y, uv.z, uv.w};
        #pragma unroll
        for (int c = 0; c < 4; c++) {
            float g2 = qdq16(silu_t(rg[c], sg), st);
            float u  = qdq16(ru[c], su);
            m = fmaxf(m, fabsf(g2 * u));
        }
    }
    #pragma unroll
    for (int o = 16; o; o >>= 1) m = fmaxf(m, __shfl_xor_sync(0xffffffffu, m, o));
    __shared__ float red[32];
    int wid = threadIdx.x >> 5, lid = threadIdx.x & 31;
    if (lid == 0) red[wid] = m;
    __syncthreads();
    if (threadIdx.x == 0) {
        int nw = (blockDim.x + 31) >> 5;
        float mm = red[0];
        for (int i = 1; i < nw; i++) mm = fmaxf(mm, red[i]);
        atomicMax(&g_amax[4], __float_as_uint(mm));
    }
}

// Pass 3: recompute p, qdq final, split-write fp16 ph/pl
__global__ void k_write_p(const float4* __restrict__ gate,
                          const float4* __restrict__ up,
                          __half2* __restrict__ ph,
                          __half2* __restrict__ pl, size_t n4) {
    float sg = scale16(__uint_as_float(g_amax[2]));
    float st = scale16(__uint_as_float(g_amax[3]));
    float su = scale16(__uint_as_float(g_amax[1]));
    float sp = scale16(__uint_as_float(g_amax[4]));
    for (size_t i = (size_t)blockIdx.x * blockDim.x + threadIdx.x; i < n4;
         i += (size_t)gridDim.x * blockDim.x) {
        float4 gv = gate[i];
        float4 uv = up[i];
        float rg[4] = {gv.x, gv.y, gv.z, gv.w};
        float ru[4] = {uv.x, uv.y, uv.z, uv.w};
        __half hh[4], ll[4];
        #pragma unroll
        for (int c = 0; c < 4; c++) {
            float g2 = qdq16(silu_t(rg[c], sg), st);
            float u  = qdq16(ru[c], su);
            float o  = qdq16(g2 * u, sp);
            hh[c] = __float2half_rn(o);
            ll[c] = __float2half_rn(o - __half2float(hh[c]));
        }
        ph[2 * i]     = __halves2half2(hh[0], hh[1]);
        ph[2 * i + 1] = __halves2half2(hh[2], hh[3]);
        pl[2 * i]     = __halves2half2(ll[0], ll[1]);
        pl[2 * i + 1] = __halves2half2(ll[2], ll[3]);
    }
}

// ---------------------------------------------------------------------------
// Host launch
// ---------------------------------------------------------------------------
extern "C" void kernel_launch(void* const* d_in, const int* in_sizes, int n_in,
                              void* d_out, int out_size)
{
    const float* x  = (const float*)d_in[0];
    const float* wg = (const float*)d_in[1];
    const float* wu = (const float*)d_in[2];
    const float* wd = (const float*)d_in[3];
    float* out = (float*)d_out;

    __half *p_xh, *p_xl, *p_wu, *p_wg, *p_wd, *p_ph, *p_pl;
    float *p_up, *p_gate;
    unsigned int* p_amax;
    cudaGetSymbolAddress((void**)&p_xh,  g_xh);
    cudaGetSymbolAddress((void**)&p_xl,  g_xl);
    cudaGetSymbolAddress((void**)&p_wu,  g_wu);
    cudaGetSymbolAddress((void**)&p_wg,  g_wg);
    cudaGetSymbolAddress((void**)&p_wd,  g_wd);
    cudaGetSymbolAddress((void**)&p_ph,  g_ph);
    cudaGetSymbolAddress((void**)&p_pl,  g_pl);
    cudaGetSymbolAddress((void**)&p_up,  g_up);
    cudaGetSymbolAddress((void**)&p_gate, g_gate);
    cudaGetSymbolAddress((void**)&p_amax, g_amax);

    cudaFuncSetAttribute(gemm_fp16_split,
                         cudaFuncAttributeMaxDynamicSharedMemorySize, GEMM_DYN_SMEM);

    const size_t nx4 = (size_t)M_TOK * H_DIM / 4;
    const size_t ni4 = (size_t)M_TOK * I_DIM / 4;
    const int nw4 = (I_DIM * H_DIM) / 4;

    k_zero_amax<<<1, 8>>>();
    k_amax<<<2048, 256>>>((const float4*)x, nx4, 0);
    k_quant_split<<<2048, 256>>>((const float4*)x, (__half2*)p_xh,
                                 (__half2*)p_xl, nx4, 0);
    k_dequant_w<<<nw4 / 256, 256>>>((const float4*)wu, (__half2*)p_wu, nw4);
    k_dequant_w<<<nw4 / 256, 256>>>((const float4*)wg, (__half2*)p_wg, nw4);

    // up GEMM
    {
        dim3 grid(I_DIM / 128, M_TOK / 128);     // (24, 64)
        gemm_fp16_split<<<grid, GTHREADS, GEMM_DYN_SMEM>>>(
            p_xh, p_xl, p_wu, p_up, I_DIM, H_DIM, p_amax + 1);
    }
    // gate GEMM
    {
        dim3 grid(I_DIM / 128, M_TOK / 128);
        gemm_fp16_split<<<grid, GTHREADS, GEMM_DYN_SMEM>>>(
            p_xh, p_xl, p_wg, p_gate, I_DIM, H_DIM, p_amax + 2);
    }
    k_dequant_w<<<nw4 / 256, 256>>>((const float4*)wd, (__half2*)p_wd, nw4);

    // SiLU chain (recompute; no t/p materialization)
    k_amax_t<<<4096, 256>>>((const float4*)p_gate, ni4);
    k_amax_p<<<4096, 256>>>((const float4*)p_gate, (const float4*)p_up, ni4);
    k_write_p<<<4096, 256>>>((const float4*)p_gate, (const float4*)p_up,
                             (__half2*)p_ph, (__half2*)p_pl, ni4);

    // down GEMM
    {
        dim3 grid(H_DIM / 128, M_TOK / 128);     // (8, 64)
        gemm_fp16_split<<<grid, GTHREADS, GEMM_DYN_SMEM>>>(
            p_ph, p_pl, p_wd, out, H_DIM, I_DIM, nullptr);
    }
}

// round 13
// speedup vs baseline: 1.3152x; 1.1545x over previous
#include <cuda_runtime.h>
#include <cuda_fp16.h>
#include <math.h>
#include <stdint.h>

// ---------------------------------------------------------------------------
// Problem shape (fixed): B=2, S=4096, H=1024, I=3072
// ---------------------------------------------------------------------------
#define M_TOK 8192
#define H_DIM 1024
#define I_DIM 3072
#define NI2   (2 * I_DIM)          // 6144 (fused up|gate)

// ---------------------------------------------------------------------------
// Scratch
// ---------------------------------------------------------------------------
__device__ __half g_xh [(size_t)M_TOK * H_DIM];
__device__ __half g_xl [(size_t)M_TOK * H_DIM];
__device__ __half g_wug[(size_t)NI2 * H_DIM];     // [wu rows 0..3071 | wg rows 3072..6143]
__device__ __half g_wd [(size_t)H_DIM * I_DIM];
__device__ float  g_ug [(size_t)M_TOK * NI2];     // fused raw output [8192, 6144]
__device__ __half g_ph [(size_t)M_TOK * I_DIM];
__device__ unsigned int g_amax[8];
// slots: 0=x  1=up_raw  2=gate_raw  3=t  4=p

// ---------------------------------------------------------------------------
// Helpers
// ---------------------------------------------------------------------------
__device__ __forceinline__ float qdq16(float v, float scale) {
    float q = rintf(__fdiv_rn(v, scale));
    q = fminf(fmaxf(q, -32768.0f), 32767.0f);
    return q * scale;
}
__device__ __forceinline__ float scale16(float amax) {
    return fmaxf(__fdiv_rn(amax, 32767.0f), 1e-12f);
}
__device__ __forceinline__ float silu_t(float graw, float sg) {
    float g1 = qdq16(graw, sg);
    float sig = __fdiv_rn(1.0f, 1.0f + expf(-g1));
    sig = fminf(fmaxf(rintf(sig * 65536.0f), 0.0f), 65535.0f) * (1.0f / 65536.0f);
    return g1 * sig;
}
__device__ __forceinline__ uint32_t smem_u32(const void* p) {
    uint32_t a;
    asm("{ .reg .u64 t; cvta.to.shared.u64 t, %1; cvt.u32.u64 %0, t; }"
        : "=r"(a) : "l"(p));
    return a;
}
__device__ __forceinline__ void cp16(uint32_t dst, const void* src) {
    asm volatile("cp.async.cg.shared.global [%0], [%1], 16;"
                 :: "r"(dst), "l"(src) : "memory");
}
__device__ __forceinline__ void ldsm_x4(uint32_t addr, uint32_t* r) {
    asm volatile("ldmatrix.sync.aligned.m8n8.x4.shared.b16 {%0,%1,%2,%3}, [%4];"
                 : "=r"(r[0]), "=r"(r[1]), "=r"(r[2]), "=r"(r[3]) : "r"(addr));
}
__device__ __forceinline__ void mma16816(float* c, const uint32_t* a,
                                         uint32_t b0, uint32_t b1) {
    asm volatile(
        "mma.sync.aligned.m16n8k16.row.col.f32.f16.f16.f32 "
        "{%0,%1,%2,%3}, {%4,%5,%6,%7}, {%8,%9}, {%0,%1,%2,%3};"
        : "+f"(c[0]), "+f"(c[1]), "+f"(c[2]), "+f"(c[3])
        : "r"(a[0]), "r"(a[1]), "r"(a[2]), "r"(a[3]), "r"(b0), "r"(b1));
}

// ---------------------------------------------------------------------------
// 2-term GEMM: C[M,N] = (Ah+Al)[M,K] @ Wh[N,K]^T    (fused up|gate)
// 128x128 CTA tile, 128 threads (4 warps, 64x64 warp tiles), 2-stage,
// 96KB smem -> 2 CTAs/SM. amax epilogue slot picked by n-half (up vs gate).
// ---------------------------------------------------------------------------
#define NSTAGES2 2
#define TILE_BYTES 16384
#define STAGE2_BYTES (3 * TILE_BYTES)
#define GEMM2_DYN_SMEM (NSTAGES2 * STAGE2_BYTES + 1024)
#define GTHREADS 128

__device__ __forceinline__ void load_chunk2(
    uint32_t sbase,
    const __half* __restrict__ Ah, const __half* __restrict__ Al,
    const __half* __restrict__ Bh,
    int m0, int n0, int K, int k0, int tid)
{
    #pragma unroll
    for (int u = tid; u < 1024; u += GTHREADS) {
        int r = u >> 3, cc = u & 7;
        uint32_t off = (uint32_t)(r * 128 + cc * 16);
        uint32_t sw = off ^ ((off >> 3) & 0x70);
        size_t arow = (size_t)(m0 + r) * K + k0 + cc * 8;
        size_t brow = (size_t)(n0 + r) * K + k0 + cc * 8;
        cp16(sbase + sw,                  Ah + arow);
        cp16(sbase + TILE_BYTES + sw,     Al + arow);
        cp16(sbase + 2 * TILE_BYTES + sw, Bh + brow);
    }
}

__global__ void __launch_bounds__(GTHREADS, 2)
gemm_fp16_split(const __half* __restrict__ Ah, const __half* __restrict__ Al,
                const __half* __restrict__ Bh,
                float* __restrict__ C, int N, int K, unsigned int* amax_base)
{
    extern __shared__ char dynsmem[];
    __shared__ float s_red[4];
    const int tid = threadIdx.x;
    const int wid = tid >> 5;
    const int lid = tid & 31;
    const int m0 = blockIdx.y * 128;
    const int n0 = blockIdx.x * 128;
    const int NC = K >> 6;
    uint32_t dynbase = smem_u32(dynsmem);
    dynbase = (dynbase + 1023u) & ~1023u;

    const int m0w = (wid & 1) * 64;
    const int n0w = (wid >> 1) * 64;
    float acc[4][8][4];
    #pragma unroll
    for (int i = 0; i < 4; i++)
        #pragma unroll
        for (int j = 0; j < 8; j++)
            #pragma unroll
            for (int q = 0; q < 4; q++) acc[i][j][q] = 0.0f;

    const int g  = lid >> 3;
    const int lr = lid & 7;
    const int rsel = (g & 1) * 8 + lr;
    const int csel = (g >> 1) * 16;

    #pragma unroll
    for (int c = 0; c < NSTAGES2; c++) {
        load_chunk2(dynbase + c * STAGE2_BYTES, Ah, Al, Bh, m0, n0, K, c * 64, tid);
        asm volatile("cp.async.commit_group;" ::: "memory");
    }

    for (int c = 0; c < NC; ++c) {
        int s = c & (NSTAGES2 - 1);
        asm volatile("cp.async.wait_group %0;" :: "n"(NSTAGES2 - 1) : "memory");
        __syncthreads();
        uint32_t sb = dynbase + s * STAGE2_BYTES;
        uint32_t aH = sb, aL = sb + TILE_BYTES;
        uint32_t bH = sb + 2 * TILE_BYTES;

        #pragma unroll
        for (int ks = 0; ks < 4; ks++) {
            const int cb = ks * 32 + csel;
            uint32_t ah[4][4], al[4][4];
            #pragma unroll
            for (int mt = 0; mt < 4; mt++) {
                uint32_t off = (uint32_t)((m0w + mt * 16 + rsel) * 128 + cb);
                uint32_t sw = off ^ ((off >> 3) & 0x70);
                ldsm_x4(aH + sw, ah[mt]);
                ldsm_x4(aL + sw, al[mt]);
            }
            #pragma unroll
            for (int np = 0; np < 4; np++) {
                uint32_t off = (uint32_t)((n0w + np * 16 + rsel) * 128 + cb);
                uint32_t sw = off ^ ((off >> 3) & 0x70);
                uint32_t bh[4];
                ldsm_x4(bH + sw, bh);
                #pragma unroll
                for (int mt = 0; mt < 4; mt++) {
                    mma16816(acc[mt][np * 2 + 0], ah[mt], bh[0], bh[2]);
                    mma16816(acc[mt][np * 2 + 1], ah[mt], bh[1], bh[3]);
                    mma16816(acc[mt][np * 2 + 0], al[mt], bh[0], bh[2]);
                    mma16816(acc[mt][np * 2 + 1], al[mt], bh[1], bh[3]);
                }
            }
        }
        __syncthreads();
        if (c + NSTAGES2 < NC)
            load_chunk2(dynbase + s * STAGE2_BYTES, Ah, Al, Bh, m0, n0, K,
                        (c + NSTAGES2) * 64, tid);
        asm volatile("cp.async.commit_group;" ::: "memory");
    }

    // epilogue
    const int gq = lid >> 2, q4 = lid & 3;
    float lmax = 0.0f;
    #pragma unroll
    for (int mt = 0; mt < 4; mt++) {
        #pragma unroll
        for (int nt = 0; nt < 8; nt++) {
            float* cp0 = C + (size_t)(m0 + m0w + mt * 16 + gq) * N
                           + n0 + n0w + nt * 8 + q4 * 2;
            float* cp1 = cp0 + 8 * (size_t)N;
            cp0[0] = acc[mt][nt][0]; cp0[1] = acc[mt][nt][1];
            cp1[0] = acc[mt][nt][2]; cp1[1] = acc[mt][nt][3];
            #pragma unroll
            for (int q = 0; q < 4; q++)
                lmax = fmaxf(lmax, fabsf(acc[mt][nt][q]));
        }
    }
    if (amax_base) {
        #pragma unroll
        for (int o = 16; o; o >>= 1)
            lmax = fmaxf(lmax, __shfl_xor_sync(0xffffffffu, lmax, o));
        if (lid == 0) s_red[wid] = lmax;
        __syncthreads();
        if (tid == 0) {
            float m = s_red[0];
            #pragma unroll
            for (int i = 1; i < 4; i++) m = fmaxf(m, s_red[i]);
            unsigned int* slot = amax_base + (n0 >= I_DIM ? 1 : 0);
            atomicMax(slot, __float_as_uint(m));
        }
    }
}

// ---------------------------------------------------------------------------
// 1-term GEMM (down): C[M,N] = Ah[M,K] @ Wh[N,K]^T
// 128x128 tile, 128 threads, 3-stage (32KB/stage) -> 96KB, 2 CTAs/SM.
// ---------------------------------------------------------------------------
#define NSTAGES1 3
#define STAGE1_BYTES (2 * TILE_BYTES)
#define GEMM1_DYN_SMEM (NSTAGES1 * STAGE1_BYTES + 1024)

__device__ __forceinline__ void load_chunk1(
    uint32_t sbase,
    const __half* __restrict__ Ah, const __half* __restrict__ Bh,
    int m0, int n0, int K, int k0, int tid)
{
    #pragma unroll
    for (int u = tid; u < 1024; u += GTHREADS) {
        int r = u >> 3, cc = u & 7;
        uint32_t off = (uint32_t)(r * 128 + cc * 16);
        uint32_t sw = off ^ ((off >> 3) & 0x70);
        size_t arow = (size_t)(m0 + r) * K + k0 + cc * 8;
        size_t brow = (size_t)(n0 + r) * K + k0 + cc * 8;
        cp16(sbase + sw,              Ah + arow);
        cp16(sbase + TILE_BYTES + sw, Bh + brow);
    }
}

__global__ void __launch_bounds__(GTHREADS, 2)
gemm_fp16_1term(const __half* __restrict__ Ah, const __half* __restrict__ Bh,
                float* __restrict__ C, int N, int K)
{
    extern __shared__ char dynsmem[];
    const int tid = threadIdx.x;
    const int wid = tid >> 5;
    const int lid = tid & 31;
    const int m0 = blockIdx.y * 128;
    const int n0 = blockIdx.x * 128;
    const int NC = K >> 6;
    uint32_t dynbase = smem_u32(dynsmem);
    dynbase = (dynbase + 1023u) & ~1023u;

    const int m0w = (wid & 1) * 64;
    const int n0w = (wid >> 1) * 64;
    float acc[4][8][4];
    #pragma unroll
    for (int i = 0; i < 4; i++)
        #pragma unroll
        for (int j = 0; j < 8; j++)
            #pragma unroll
            for (int q = 0; q < 4; q++) acc[i][j][q] = 0.0f;

    const int g  = lid >> 3;
    const int lr = lid & 7;
    const int rsel = (g & 1) * 8 + lr;
    const int csel = (g >> 1) * 16;

    #pragma unroll
    for (int c = 0; c < NSTAGES1; c++) {
        load_chunk1(dynbase + c * STAGE1_BYTES, Ah, Bh, m0, n0, K, c * 64, tid);
        asm volatile("cp.async.commit_group;" ::: "memory");
    }

    for (int c = 0; c < NC; ++c) {
        int s = c - (c / NSTAGES1) * NSTAGES1;
        asm volatile("cp.async.wait_group %0;" :: "n"(NSTAGES1 - 1) : "memory");
        __syncthreads();
        uint32_t sb = dynbase + s * STAGE1_BYTES;
        uint32_t aH = sb, bH = sb + TILE_BYTES;

        #pragma unroll
        for (int ks = 0; ks < 4; ks++) {
            const int cb = ks * 32 + csel;
            uint32_t ah[4][4];
            #pragma unroll
            for (int mt = 0; mt < 4; mt++) {
                uint32_t off = (uint32_t)((m0w + mt * 16 + rsel) * 128 + cb);
                uint32_t sw = off ^ ((off >> 3) & 0x70);
                ldsm_x4(aH + sw, ah[mt]);
            }
            #pragma unroll
            for (int np = 0; np < 4; np++) {
                uint32_t off = (uint32_t)((n0w + np * 16 + rsel) * 128 + cb);
                uint32_t sw = off ^ ((off >> 3) & 0x70);
                uint32_t bh[4];
                ldsm_x4(bH + sw, bh);
                #pragma unroll
                for (int mt = 0; mt < 4; mt++) {
                    mma16816(acc[mt][np * 2 + 0], ah[mt], bh[0], bh[2]);
                    mma16816(acc[mt][np * 2 + 1], ah[mt], bh[1], bh[3]);
                }
            }
        }
        __syncthreads();
        if (c + NSTAGES1 < NC)
            load_chunk1(dynbase + s * STAGE1_BYTES, Ah, Bh, m0, n0, K,
                        (c + NSTAGES1) * 64, tid);
        asm volatile("cp.async.commit_group;" ::: "memory");
    }

    const int gq = lid >> 2, q4 = lid & 3;
    #pragma unroll
    for (int mt = 0; mt < 4; mt++) {
        #pragma unroll
        for (int nt = 0; nt < 8; nt++) {
            float* cp0 = C + (size_t)(m0 + m0w + mt * 16 + gq) * N
                           + n0 + n0w + nt * 8 + q4 * 2;
            float* cp1 = cp0 + 8 * (size_t)N;
            cp0[0] = acc[mt][nt][0]; cp0[1] = acc[mt][nt][1];
            cp1[0] = acc[mt][nt][2]; cp1[1] = acc[mt][nt][3];
        }
    }
}

// ---------------------------------------------------------------------------
// Elementwise
// ---------------------------------------------------------------------------
__global__ void k_zero_amax() {
    if (threadIdx.x < 8) g_amax[threadIdx.x] = 0u;
}

__global__ void k_amax(const float4* __restrict__ p, size_t n4, int slot) {
    float m = 0.0f;
    for (size_t i = (size_t)blockIdx.x * blockDim.x + threadIdx.x; i < n4;
         i += (size_t)gridDim.x * blockDim.x) {
        float4 v = p[i];
        m = fmaxf(m, fmaxf(fmaxf(fabsf(v.x), fabsf(v.y)),
                           fmaxf(fabsf(v.z), fabsf(v.w))));
    }
    #pragma unroll
    for (int o = 16; o; o >>= 1) m = fmaxf(m, __shfl_xor_sync(0xffffffffu, m, o));
    __shared__ float red[32];
    int wid = threadIdx.x >> 5, lid = threadIdx.x & 31;
    if (lid == 0) red[wid] = m;
    __syncthreads();
    if (threadIdx.x == 0) {
        int nw = (blockDim.x + 31) >> 5;
        float mm = red[0];
        for (int i = 1; i < nw; i++) mm = fmaxf(mm, red[i]);
        atomicMax(&g_amax[slot], __float_as_uint(mm));
    }
}

__global__ void k_quant_split(const float4* __restrict__ in,
                              __half2* __restrict__ h,
                              __half2* __restrict__ l,
                              size_t n4, int slot) {
    float s = scale16(__uint_as_float(g_amax[slot]));
    for (size_t i = (size_t)blockIdx.x * blockDim.x + threadIdx.x; i < n4;
         i += (size_t)gridDim.x * blockDim.x) {
        float4 v = in[i];
        float q[4] = {qdq16(v.x, s), qdq16(v.y, s), qdq16(v.z, s), qdq16(v.w, s)};
        __half hh[4], ll[4];
        #pragma unroll
        for (int c = 0; c < 4; c++) {
            hh[c] = __float2half_rn(q[c]);
            ll[c] = __float2half_rn(q[c] - __half2float(hh[c]));
        }
        h[2 * i]     = __halves2half2(hh[0], hh[1]);
        h[2 * i + 1] = __halves2half2(hh[2], hh[3]);
        l[2 * i]     = __halves2half2(ll[0], ll[1]);
        l[2 * i + 1] = __halves2half2(ll[2], ll[3]);
    }
}

__global__ void k_dequant_w(const float4* __restrict__ w,
                            __half2* __restrict__ oh, int n4) {
    int i = blockIdx.x * blockDim.x + threadIdx.x;
    if (i >= n4) return;
    float4 v = w[i];
    float r[4] = {v.x, v.y, v.z, v.w};
    float a = fmaxf(fmaxf(fabsf(r[0]), fabsf(r[1])),
                    fmaxf(fabsf(r[2]), fabsf(r[3])));
    #pragma unroll
    for (int o = 1; o < 8; o <<= 1)
        a = fmaxf(a, __shfl_xor_sync(0xffffffffu, a, o));
    float s = fmaxf(__fdiv_rn(a, 7.0f), 1e-12f);
    __half hh[4];
    #pragma unroll
    for (int c = 0; c < 4; c++) {
        float q = rintf(__fdiv_rn(r[c], s));
        q = fminf(fmaxf(q, -8.0f), 7.0f);
        hh[c] = __float2half_rn(q * s);
    }
    oh[2 * i]     = __halves2half2(hh[0], hh[1]);
    oh[2 * i + 1] = __halves2half2(hh[2], hh[3]);
}

// Interleaved layout: C[8192, 6144]; up = cols [0,3072), gate = cols [3072,6144)
#define ROW4 1536      // float4 per row of C
#define HALF4 768      // float4 per half-row

// Pass 1: amax(t) from gate half
__global__ void k_amax_t(const float4* __restrict__ C, size_t n4) {
    float sg = scale16(__uint_as_float(g_amax[2]));
    float m = 0.0f;
    for (size_t i = (size_t)blockIdx.x * blockDim.x + threadIdx.x; i < n4;
         i += (size_t)gridDim.x * blockDim.x) {
        size_t mm_ = i / HALF4, j = i - mm_ * HALF4;
        float4 v = C[mm_ * ROW4 + HALF4 + j];
        m = fmaxf(m, fabsf(silu_t(v.x, sg)));
        m = fmaxf(m, fabsf(silu_t(v.y, sg)));
        m = fmaxf(m, fabsf(silu_t(v.z, sg)));
        m = fmaxf(m, fabsf(silu_t(v.w, sg)));
    }
    #pragma unroll
    for (int o = 16; o; o >>= 1) m = fmaxf(m, __shfl_xor_sync(0xffffffffu, m, o));
    __shared__ float red[32];
    int wid = threadIdx.x >> 5, lid = threadIdx.x & 31;
    if (lid == 0) red[wid] = m;
    __syncthreads();
    if (threadIdx.x == 0) {
        int nw = (blockDim.x + 31) >> 5;
        float mm = red[0];
        for (int i = 1; i < nw; i++) mm = fmaxf(mm, red[i]);
        atomicMax(&g_amax[3], __float_as_uint(mm));
    }
}

// Pass 2: amax(p)
__global__ void k_amax_p(const float4* __restrict__ C, size_t n4) {
    float sg = scale16(__uint_as_float(g_amax[2]));
    float st = scale16(__uint_as_float(g_amax[3]));
    float su = scale16(__uint_as_float(g_amax[1]));
    float m = 0.0f;
    for (size_t i = (size_t)blockIdx.x * blockDim.x + threadIdx.x; i < n4;
         i += (size_t)gridDim.x * blockDim.x) {
        size_t mm_ = i / HALF4, j = i - mm_ * HALF4;
        float4 uv = C[mm_ * ROW4 + j];
        float4 gv = C[mm_ * ROW4 + HALF4 + j];
        float rg[4] = {gv.x, gv.y, gv.z, gv.w};
        float ru[4] = {uv.x, uv.y, uv.z, uv.w};
        #pragma unroll
        for (int c = 0; c < 4; c++) {
            float g2 = qdq16(silu_t(rg[c], sg), st);
            float u  = qdq16(ru[c], su);
            m = fmaxf(m, fabsf(g2 * u));
        }
    }
    #pragma unroll
    for (int o = 16; o; o >>= 1) m = fmaxf(m, __shfl_xor_sync(0xffffffffu, m, o));
    __shared__ float red[32];
    int wid = threadIdx.x >> 5, lid = threadIdx.x & 31;
    if (lid == 0) red[wid] = m;
    __syncthreads();
    if (threadIdx.x == 0) {
        int nw = (blockDim.x + 31) >> 5;
        float mm = red[0];
        for (int i = 1; i < nw; i++) mm = fmaxf(mm, red[i]);
        atomicMax(&g_amax[4], __float_as_uint(mm));
    }
}

// Pass 3: recompute p, qdq final, write fp16 ph (single term; pl dropped)
__global__ void k_write_p(const float4* __restrict__ C,
                          __half2* __restrict__ ph, size_t n4) {
    float sg = scale16(__uint_as_float(g_amax[2]));
    float st = scale16(__uint_as_float(g_amax[3]));
    float su = scale16(__uint_as_float(g_amax[1]));
    float sp = scale16(__uint_as_float(g_amax[4]));
    for (size_t i = (size_t)blockIdx.x * blockDim.x + threadIdx.x; i < n4;
         i += (size_t)gridDim.x * blockDim.x) {
        size_t mm_ = i / HALF4, j = i - mm_ * HALF4;
        float4 uv = C[mm_ * ROW4 + j];
        float4 gv = C[mm_ * ROW4 + HALF4 + j];
        float rg[4] = {gv.x, gv.y, gv.z, gv.w};
        float ru[4] = {uv.x, uv.y, uv.z, uv.w};
        __half hh[4];
        #pragma unroll
        for (int c = 0; c < 4; c++) {
            float g2 = qdq16(silu_t(rg[c], sg), st);
            float u  = qdq16(ru[c], su);
            float o  = qdq16(g2 * u, sp);
            hh[c] = __float2half_rn(o);
        }
        ph[2 * i]     = __halves2half2(hh[0], hh[1]);
        ph[2 * i + 1] = __halves2half2(hh[2], hh[3]);
    }
}

// ---------------------------------------------------------------------------
// Host launch
// ---------------------------------------------------------------------------
extern "C" void kernel_launch(void* const* d_in, const int* in_sizes, int n_in,
                              void* d_out, int out_size)
{
    const float* x  = (const float*)d_in[0];
    const float* wg = (const float*)d_in[1];
    const float* wu = (const float*)d_in[2];
    const float* wd = (const float*)d_in[3];
    float* out = (float*)d_out;

    __half *p_xh, *p_xl, *p_wug, *p_wd, *p_ph;
    float *p_ug;
    unsigned int* p_amax;
    cudaGetSymbolAddress((void**)&p_xh,  g_xh);
    cudaGetSymbolAddress((void**)&p_xl,  g_xl);
    cudaGetSymbolAddress((void**)&p_wug, g_wug);
    cudaGetSymbolAddress((void**)&p_wd,  g_wd);
    cudaGetSymbolAddress((void**)&p_ph,  g_ph);
    cudaGetSymbolAddress((void**)&p_ug,  g_ug);
    cudaGetSymbolAddress((void**)&p_amax, g_amax);

    cudaFuncSetAttribute(gemm_fp16_split,
                         cudaFuncAttributeMaxDynamicSharedMemorySize, GEMM2_DYN_SMEM);
    cudaFuncSetAttribute(gemm_fp16_1term,
                         cudaFuncAttributeMaxDynamicSharedMemorySize, GEMM1_DYN_SMEM);

    const size_t nx4 = (size_t)M_TOK * H_DIM / 4;
    const size_t ni4 = (size_t)M_TOK * I_DIM / 4;   // per-half float4 count
    const int nw4 = (I_DIM * H_DIM) / 4;

    k_zero_amax<<<1, 8>>>();
    k_amax<<<2048, 256>>>((const float4*)x, nx4, 0);
    k_quant_split<<<2048, 256>>>((const float4*)x, (__half2*)p_xh,
                                 (__half2*)p_xl, nx4, 0);
    // weights into one buffer: wu -> rows [0,3072), wg -> rows [3072,6144)
    k_dequant_w<<<nw4 / 256, 256>>>((const float4*)wu, (__half2*)p_wug, nw4);
    k_dequant_w<<<nw4 / 256, 256>>>((const float4*)wg,
                                    (__half2*)(p_wug + (size_t)I_DIM * H_DIM), nw4);

    // fused up|gate GEMM: C[8192, 6144]
    {
        dim3 grid(NI2 / 128, M_TOK / 128);     // (48, 64)
        gemm_fp16_split<<<grid, GTHREADS, GEMM2_DYN_SMEM>>>(
            p_xh, p_xl, p_wug, p_ug, NI2, H_DIM, p_amax + 1);
    }
    k_dequant_w<<<nw4 / 256, 256>>>((const float4*)wd, (__half2*)p_wd, nw4);

    // SiLU chain on interleaved layout (recompute; ph only, pl dropped)
    k_amax_t<<<4096, 256>>>((const float4*)p_ug, ni4);
    k_amax_p<<<4096, 256>>>((const float4*)p_ug, ni4);
    k_write_p<<<4096, 256>>>((const float4*)p_ug, (__half2*)p_ph, ni4);

    // down GEMM (single term)
    {
        dim3 grid(H_DIM / 128, M_TOK / 128);   // (8, 64)
        gemm_fp16_1term<<<grid, GTHREADS, GEMM1_DYN_SMEM>>>(
            p_ph, p_wd, out, H_DIM, I_DIM);
    }
}

// round 14
// speedup vs baseline: 1.7209x; 1.3085x over previous
#include <cuda_runtime.h>
#include <cuda_fp16.h>
#include <math.h>
#include <stdint.h>

// ---------------------------------------------------------------------------
// Problem shape (fixed): B=2, S=4096, H=1024, I=3072
// ---------------------------------------------------------------------------
#define M_TOK 8192
#define H_DIM 1024
#define I_DIM 3072
#define NI2   (2 * I_DIM)          // 6144 (fused up|gate)

// ---------------------------------------------------------------------------
// Scratch
// ---------------------------------------------------------------------------
__device__ __half g_xh [(size_t)M_TOK * H_DIM];
__device__ __half g_wug[(size_t)NI2 * H_DIM];     // [wu rows | wg rows]
__device__ __half g_wd [(size_t)H_DIM * I_DIM];
__device__ float  g_ug [(size_t)M_TOK * NI2];     // fused raw output [8192, 6144]
__device__ __half g_ph [(size_t)M_TOK * I_DIM];
__device__ unsigned int g_amax[8];
// slots: 0=x  1=up_raw  2=gate_raw  3=t  4=p

// ---------------------------------------------------------------------------
// Helpers
// ---------------------------------------------------------------------------
__device__ __forceinline__ float qdq16(float v, float scale) {
    float q = rintf(__fdiv_rn(v, scale));
    q = fminf(fmaxf(q, -32768.0f), 32767.0f);
    return q * scale;
}
__device__ __forceinline__ float scale16(float amax) {
    return fmaxf(__fdiv_rn(amax, 32767.0f), 1e-12f);
}
__device__ __forceinline__ float silu_t(float graw, float sg) {
    float g1 = qdq16(graw, sg);
    float sig = __fdiv_rn(1.0f, 1.0f + expf(-g1));
    sig = fminf(fmaxf(rintf(sig * 65536.0f), 0.0f), 65535.0f) * (1.0f / 65536.0f);
    return g1 * sig;
}
__device__ __forceinline__ uint32_t smem_u32(const void* p) {
    uint32_t a;
    asm("{ .reg .u64 t; cvta.to.shared.u64 t, %1; cvt.u32.u64 %0, t; }"
        : "=r"(a) : "l"(p));
    return a;
}
__device__ __forceinline__ void cp16(uint32_t dst, const void* src) {
    asm volatile("cp.async.cg.shared.global [%0], [%1], 16;"
                 :: "r"(dst), "l"(src) : "memory");
}
__device__ __forceinline__ void ldsm_x4(uint32_t addr, uint32_t* r) {
    asm volatile("ldmatrix.sync.aligned.m8n8.x4.shared.b16 {%0,%1,%2,%3}, [%4];"
                 : "=r"(r[0]), "=r"(r[1]), "=r"(r[2]), "=r"(r[3]) : "r"(addr));
}
__device__ __forceinline__ void mma16816(float* c, const uint32_t* a,
                                         uint32_t b0, uint32_t b1) {
    asm volatile(
        "mma.sync.aligned.m16n8k16.row.col.f32.f16.f16.f32 "
        "{%0,%1,%2,%3}, {%4,%5,%6,%7}, {%8,%9}, {%0,%1,%2,%3};"
        : "+f"(c[0]), "+f"(c[1]), "+f"(c[2]), "+f"(c[3])
        : "r"(a[0]), "r"(a[1]), "r"(a[2]), "r"(a[3]), "r"(b0), "r"(b1));
}

// ---------------------------------------------------------------------------
// 1-term GEMM: C[M,N] = Ah[M,K] @ Wh[N,K]^T   (fp16, fp32 accumulate)
// 128x128 tile, 128 threads (4 warps, 64x64 warp tiles), 3-stage (32KB/stage),
// 96KB smem -> 2 CTAs/SM. Optional amax epilogue (slot by n-half for up|gate).
// ---------------------------------------------------------------------------
#define TILE_BYTES 16384
#define NSTAGES 3
#define STAGE_BYTES (2 * TILE_BYTES)
#define GEMM_DYN_SMEM (NSTAGES * STAGE_BYTES + 1024)
#define GTHREADS 128

__device__ __forceinline__ void load_chunk(
    uint32_t sbase,
    const __half* __restrict__ Ah, const __half* __restrict__ Bh,
    int m0, int n0, int K, int k0, int tid)
{
    #pragma unroll
    for (int u = tid; u < 1024; u += GTHREADS) {
        int r = u >> 3, cc = u & 7;
        uint32_t off = (uint32_t)(r * 128 + cc * 16);
        uint32_t sw = off ^ ((off >> 3) & 0x70);
        size_t arow = (size_t)(m0 + r) * K + k0 + cc * 8;
        size_t brow = (size_t)(n0 + r) * K + k0 + cc * 8;
        cp16(sbase + sw,              Ah + arow);
        cp16(sbase + TILE_BYTES + sw, Bh + brow);
    }
}

__global__ void __launch_bounds__(GTHREADS, 2)
gemm_fp16_1term(const __half* __restrict__ Ah, const __half* __restrict__ Bh,
                float* __restrict__ C, int N, int K, unsigned int* amax_base)
{
    extern __shared__ char dynsmem[];
    __shared__ float s_red[4];
    const int tid = threadIdx.x;
    const int wid = tid >> 5;
    const int lid = tid & 31;
    const int m0 = blockIdx.y * 128;
    const int n0 = blockIdx.x * 128;
    const int NC = K >> 6;
    uint32_t dynbase = smem_u32(dynsmem);
    dynbase = (dynbase + 1023u) & ~1023u;

    const int m0w = (wid & 1) * 64;
    const int n0w = (wid >> 1) * 64;
    float acc[4][8][4];
    #pragma unroll
    for (int i = 0; i < 4; i++)
        #pragma unroll
        for (int j = 0; j < 8; j++)
            #pragma unroll
            for (int q = 0; q < 4; q++) acc[i][j][q] = 0.0f;

    const int g  = lid >> 3;
    const int lr = lid & 7;
    const int rsel = (g & 1) * 8 + lr;
    const int csel = (g >> 1) * 16;

    #pragma unroll
    for (int c = 0; c < NSTAGES; c++) {
        load_chunk(dynbase + c * STAGE_BYTES, Ah, Bh, m0, n0, K, c * 64, tid);
        asm volatile("cp.async.commit_group;" ::: "memory");
    }

    for (int c = 0; c < NC; ++c) {
        int s = c - (c / NSTAGES) * NSTAGES;
        asm volatile("cp.async.wait_group %0;" :: "n"(NSTAGES - 1) : "memory");
        __syncthreads();
        uint32_t sb = dynbase + s * STAGE_BYTES;
        uint32_t aH = sb, bH = sb + TILE_BYTES;

        #pragma unroll
        for (int ks = 0; ks < 4; ks++) {
            const int cb = ks * 32 + csel;
            uint32_t ah[4][4];
            #pragma unroll
            for (int mt = 0; mt < 4; mt++) {
                uint32_t off = (uint32_t)((m0w + mt * 16 + rsel) * 128 + cb);
                uint32_t sw = off ^ ((off >> 3) & 0x70);
                ldsm_x4(aH + sw, ah[mt]);
            }
            #pragma unroll
            for (int np = 0; np < 4; np++) {
                uint32_t off = (uint32_t)((n0w + np * 16 + rsel) * 128 + cb);
                uint32_t sw = off ^ ((off >> 3) & 0x70);
                uint32_t bh[4];
                ldsm_x4(bH + sw, bh);
                #pragma unroll
                for (int mt = 0; mt < 4; mt++) {
                    mma16816(acc[mt][np * 2 + 0], ah[mt], bh[0], bh[2]);
                    mma16816(acc[mt][np * 2 + 1], ah[mt], bh[1], bh[3]);
                }
            }
        }
        __syncthreads();
        if (c + NSTAGES < NC)
            load_chunk(dynbase + s * STAGE_BYTES, Ah, Bh, m0, n0, K,
                       (c + NSTAGES) * 64, tid);
        asm volatile("cp.async.commit_group;" ::: "memory");
    }

    const int gq = lid >> 2, q4 = lid & 3;
    float lmax = 0.0f;
    #pragma unroll
    for (int mt = 0; mt < 4; mt++) {
        #pragma unroll
        for (int nt = 0; nt < 8; nt++) {
            float* cp0 = C + (size_t)(m0 + m0w + mt * 16 + gq) * N
                           + n0 + n0w + nt * 8 + q4 * 2;
            float* cp1 = cp0 + 8 * (size_t)N;
            cp0[0] = acc[mt][nt][0]; cp0[1] = acc[mt][nt][1];
            cp1[0] = acc[mt][nt][2]; cp1[1] = acc[mt][nt][3];
            #pragma unroll
            for (int q = 0; q < 4; q++)
                lmax = fmaxf(lmax, fabsf(acc[mt][nt][q]));
        }
    }
    if (amax_base) {
        #pragma unroll
        for (int o = 16; o; o >>= 1)
            lmax = fmaxf(lmax, __shfl_xor_sync(0xffffffffu, lmax, o));
        if (lid == 0) s_red[wid] = lmax;
        __syncthreads();
        if (tid == 0) {
            float m = s_red[0];
            #pragma unroll
            for (int i = 1; i < 4; i++) m = fmaxf(m, s_red[i]);
            unsigned int* slot = amax_base + (n0 >= I_DIM ? 1 : 0);
            atomicMax(slot, __float_as_uint(m));
        }
    }
}

// ---------------------------------------------------------------------------
// Elementwise
// ---------------------------------------------------------------------------
__global__ void k_zero_amax() {
    if (threadIdx.x < 8) g_amax[threadIdx.x] = 0u;
}

__global__ void k_amax(const float4* __restrict__ p, size_t n4, int slot) {
    float m = 0.0f;
    for (size_t i = (size_t)blockIdx.x * blockDim.x + threadIdx.x; i < n4;
         i += (size_t)gridDim.x * blockDim.x) {
        float4 v = p[i];
        m = fmaxf(m, fmaxf(fmaxf(fabsf(v.x), fabsf(v.y)),
                           fmaxf(fabsf(v.z), fabsf(v.w))));
    }
    #pragma unroll
    for (int o = 16; o; o >>= 1) m = fmaxf(m, __shfl_xor_sync(0xffffffffu, m, o));
    __shared__ float red[32];
    int wid = threadIdx.x >> 5, lid = threadIdx.x & 31;
    if (lid == 0) red[wid] = m;
    __syncthreads();
    if (threadIdx.x == 0) {
        int nw = (blockDim.x + 31) >> 5;
        float mm = red[0];
        for (int i = 1; i < nw; i++) mm = fmaxf(mm, red[i]);
        atomicMax(&g_amax[slot], __float_as_uint(mm));
    }
}

// qdq16 then single fp16 round (lo term dropped)
__global__ void k_quant_h(const float4* __restrict__ in,
                          __half2* __restrict__ h, size_t n4, int slot) {
    float s = scale16(__uint_as_float(g_amax[slot]));
    for (size_t i = (size_t)blockIdx.x * blockDim.x + threadIdx.x; i < n4;
         i += (size_t)gridDim.x * blockDim.x) {
        float4 v = in[i];
        __half hh[4];
        hh[0] = __float2half_rn(qdq16(v.x, s));
        hh[1] = __float2half_rn(qdq16(v.y, s));
        hh[2] = __float2half_rn(qdq16(v.z, s));
        hh[3] = __float2half_rn(qdq16(v.w, s));
        h[2 * i]     = __halves2half2(hh[0], hh[1]);
        h[2 * i + 1] = __halves2half2(hh[2], hh[3]);
    }
}

__global__ void k_dequant_w(const float4* __restrict__ w,
                            __half2* __restrict__ oh, int n4) {
    int i = blockIdx.x * blockDim.x + threadIdx.x;
    if (i >= n4) return;
    float4 v = w[i];
    float r[4] = {v.x, v.y, v.z, v.w};
    float a = fmaxf(fmaxf(fabsf(r[0]), fabsf(r[1])),
                    fmaxf(fabsf(r[2]), fabsf(r[3])));
    #pragma unroll
    for (int o = 1; o < 8; o <<= 1)
        a = fmaxf(a, __shfl_xor_sync(0xffffffffu, a, o));
    float s = fmaxf(__fdiv_rn(a, 7.0f), 1e-12f);
    __half hh[4];
    #pragma unroll
    for (int c = 0; c < 4; c++) {
        float q = rintf(__fdiv_rn(r[c], s));
        q = fminf(fmaxf(q, -8.0f), 7.0f);
        hh[c] = __float2half_rn(q * s);
    }
    oh[2 * i]     = __halves2half2(hh[0], hh[1]);
    oh[2 * i + 1] = __halves2half2(hh[2], hh[3]);
}

// Interleaved layout: C[8192, 6144]; up = cols [0,3072), gate = cols [3072,6144)
#define ROW4 1536      // float4 per row of C
#define HALF4 768      // float4 per half-row

__global__ void k_amax_t(const float4* __restrict__ C, size_t n4) {
    float sg = scale16(__uint_as_float(g_amax[2]));
    float m = 0.0f;
    for (size_t i = (size_t)blockIdx.x * blockDim.x + threadIdx.x; i < n4;
         i += (size_t)gridDim.x * blockDim.x) {
        size_t mm_ = i / HALF4, j = i - mm_ * HALF4;
        float4 v = C[mm_ * ROW4 + HALF4 + j];
        m = fmaxf(m, fabsf(silu_t(v.x, sg)));
        m = fmaxf(m, fabsf(silu_t(v.y, sg)));
        m = fmaxf(m, fabsf(silu_t(v.z, sg)));
        m = fmaxf(m, fabsf(silu_t(v.w, sg)));
    }
    #pragma unroll
    for (int o = 16; o; o >>= 1) m = fmaxf(m, __shfl_xor_sync(0xffffffffu, m, o));
    __shared__ float red[32];
    int wid = threadIdx.x >> 5, lid = threadIdx.x & 31;
    if (lid == 0) red[wid] = m;
    __syncthreads();
    if (threadIdx.x == 0) {
        int nw = (blockDim.x + 31) >> 5;
        float mm = red[0];
        for (int i = 1; i < nw; i++) mm = fmaxf(mm, red[i]);
        atomicMax(&g_amax[3], __float_as_uint(mm));
    }
}

__global__ void k_amax_p(const float4* __restrict__ C, size_t n4) {
    float sg = scale16(__uint_as_float(g_amax[2]));
    float st = scale16(__uint_as_float(g_amax[3]));
    float su = scale16(__uint_as_float(g_amax[1]));
    float m = 0.0f;
    for (size_t i = (size_t)blockIdx.x * blockDim.x + threadIdx.x; i < n4;
         i += (size_t)gridDim.x * blockDim.x) {
        size_t mm_ = i / HALF4, j = i - mm_ * HALF4;
        float4 uv = C[mm_ * ROW4 + j];
        float4 gv = C[mm_ * ROW4 + HALF4 + j];
        float rg[4] = {gv.x, gv.y, gv.z, gv.w};
        float ru[4] = {uv.x, uv.y, uv.z, uv.w};
        #pragma unroll
        for (int c = 0; c < 4; c++) {
            float g2 = qdq16(silu_t(rg[c], sg), st);
            float u  = qdq16(ru[c], su);
            m = fmaxf(m, fabsf(g2 * u));
        }
    }
    #pragma unroll
    for (int o = 16; o; o >>= 1) m = fmaxf(m, __shfl_xor_sync(0xffffffffu, m, o));
    __shared__ float red[32];
    int wid = threadIdx.x >> 5, lid = threadIdx.x & 31;
    if (lid == 0) red[wid] = m;
    __syncthreads();
    if (threadIdx.x == 0) {
        int nw = (blockDim.x + 31) >> 5;
        float mm = red[0];
        for (int i = 1; i < nw; i++) mm = fmaxf(mm, red[i]);
        atomicMax(&g_amax[4], __float_as_uint(mm));
    }
}

__global__ void k_write_p(const float4* __restrict__ C,
                          __half2* __restrict__ ph, size_t n4) {
    float sg = scale16(__uint_as_float(g_amax[2]));
    float st = scale16(__uint_as_float(g_amax[3]));
    float su = scale16(__uint_as_float(g_amax[1]));
    float sp = scale16(__uint_as_float(g_amax[4]));
    for (size_t i = (size_t)blockIdx.x * blockDim.x + threadIdx.x; i < n4;
         i += (size_t)gridDim.x * blockDim.x) {
        size_t mm_ = i / HALF4, j = i - mm_ * HALF4;
        float4 uv = C[mm_ * ROW4 + j];
        float4 gv = C[mm_ * ROW4 + HALF4 + j];
        float rg[4] = {gv.x, gv.y, gv.z, gv.w};
        float ru[4] = {uv.x, uv.y, uv.z, uv.w};
        __half hh[4];
        #pragma unroll
        for (int c = 0; c < 4; c++) {
            float g2 = qdq16(silu_t(rg[c], sg), st);
            float u  = qdq16(ru[c], su);
            float o  = qdq16(g2 * u, sp);
            hh[c] = __float2half_rn(o);
        }
        ph[2 * i]     = __halves2half2(hh[0], hh[1]);
        ph[2 * i + 1] = __halves2half2(hh[2], hh[3]);
    }
}

// ---------------------------------------------------------------------------
// Host launch
// ---------------------------------------------------------------------------
extern "C" void kernel_launch(void* const* d_in, const int* in_sizes, int n_in,
                              void* d_out, int out_size)
{
    const float* x  = (const float*)d_in[0];
    const float* wg = (const float*)d_in[1];
    const float* wu = (const float*)d_in[2];
    const float* wd = (const float*)d_in[3];
    float* out = (float*)d_out;

    __half *p_xh, *p_wug, *p_wd, *p_ph;
    float *p_ug;
    unsigned int* p_amax;
    cudaGetSymbolAddress((void**)&p_xh,  g_xh);
    cudaGetSymbolAddress((void**)&p_wug, g_wug);
    cudaGetSymbolAddress((void**)&p_wd,  g_wd);
    cudaGetSymbolAddress((void**)&p_ph,  g_ph);
    cudaGetSymbolAddress((void**)&p_ug,  g_ug);
    cudaGetSymbolAddress((void**)&p_amax, g_amax);

    cudaFuncSetAttribute(gemm_fp16_1term,
                         cudaFuncAttributeMaxDynamicSharedMemorySize, GEMM_DYN_SMEM);

    const size_t nx4 = (size_t)M_TOK * H_DIM / 4;
    const size_t ni4 = (size_t)M_TOK * I_DIM / 4;   // per-half float4 count
    const int nw4 = (I_DIM * H_DIM) / 4;

    k_zero_amax<<<1, 8>>>();
    k_amax<<<2048, 256>>>((const float4*)x, nx4, 0);
    k_quant_h<<<2048, 256>>>((const float4*)x, (__half2*)p_xh, nx4, 0);
    // weights into one buffer: wu -> rows [0,3072), wg -> rows [3072,6144)
    k_dequant_w<<<nw4 / 256, 256>>>((const float4*)wu, (__half2*)p_wug, nw4);
    k_dequant_w<<<nw4 / 256, 256>>>((const float4*)wg,
                                    (__half2*)(p_wug + (size_t)I_DIM * H_DIM), nw4);

    // fused up|gate GEMM (single term): C[8192, 6144]
    {
        dim3 grid(NI2 / 128, M_TOK / 128);     // (48, 64)
        gemm_fp16_1term<<<grid, GTHREADS, GEMM_DYN_SMEM>>>(
            p_xh, p_wug, p_ug, NI2, H_DIM, p_amax + 1);
    }
    k_dequant_w<<<nw4 / 256, 256>>>((const float4*)wd, (__half2*)p_wd, nw4);

    // SiLU chain on interleaved layout (recompute; ph only)
    k_amax_t<<<4096, 256>>>((const float4*)p_ug, ni4);
    k_amax_p<<<4096, 256>>>((const float4*)p_ug, ni4);
    k_write_p<<<4096, 256>>>((const float4*)p_ug, (__half2*)p_ph, ni4);

    // down GEMM (single term)
    {
        dim3 grid(H_DIM / 128, M_TOK / 128);   // (8, 64)
        gemm_fp16_1term<<<grid, GTHREADS, GEMM_DYN_SMEM>>>(
            p_ph, p_wd, out, H_DIM, I_DIM, nullptr);
    }
}

// round 15
// speedup vs baseline: 1.8877x; 1.0970x over previous
#include <cuda_runtime.h>
#include <cuda_fp16.h>
#include <math.h>
#include <stdint.h>

// ---------------------------------------------------------------------------
// Problem shape (fixed): B=2, S=4096, H=1024, I=3072
// ---------------------------------------------------------------------------
#define M_TOK 8192
#define H_DIM 1024
#define I_DIM 3072
#define NI2   (2 * I_DIM)          // 6144 (fused up|gate)

// ---------------------------------------------------------------------------
// Scratch
// ---------------------------------------------------------------------------
__device__ __half g_xh [(size_t)M_TOK * H_DIM];
__device__ __half g_wug[(size_t)NI2 * H_DIM];     // [wu rows | wg rows]
__device__ __half g_wd [(size_t)H_DIM * I_DIM];
__device__ __half g_ug [(size_t)M_TOK * NI2];     // fused raw output, fp16
__device__ __half g_ph [(size_t)M_TOK * I_DIM];
__device__ unsigned int g_amax[8];
// slots: 0=x  1=up_raw  2=gate_raw  3=t  4=p  5=max_pos_gate

// ---------------------------------------------------------------------------
// Helpers
// ---------------------------------------------------------------------------
__device__ __forceinline__ float qdq16(float v, float scale) {
    float q = rintf(__fdiv_rn(v, scale));
    q = fminf(fmaxf(q, -32768.0f), 32767.0f);
    return q * scale;
}
__device__ __forceinline__ float scale16(float amax) {
    return fmaxf(__fdiv_rn(amax, 32767.0f), 1e-12f);
}
__device__ __forceinline__ float silu_t(float graw, float sg) {
    float g1 = qdq16(graw, sg);
    float sig = __fdiv_rn(1.0f, 1.0f + expf(-g1));
    sig = fminf(fmaxf(rintf(sig * 65536.0f), 0.0f), 65535.0f) * (1.0f / 65536.0f);
    return g1 * sig;
}
__device__ __forceinline__ uint32_t smem_u32(const void* p) {
    uint32_t a;
    asm("{ .reg .u64 t; cvta.to.shared.u64 t, %1; cvt.u32.u64 %0, t; }"
        : "=r"(a) : "l"(p));
    return a;
}
__device__ __forceinline__ void cp16(uint32_t dst, const void* src) {
    asm volatile("cp.async.cg.shared.global [%0], [%1], 16;"
                 :: "r"(dst), "l"(src) : "memory");
}
__device__ __forceinline__ void ldsm_x4(uint32_t addr, uint32_t* r) {
    asm volatile("ldmatrix.sync.aligned.m8n8.x4.shared.b16 {%0,%1,%2,%3}, [%4];"
                 : "=r"(r[0]), "=r"(r[1]), "=r"(r[2]), "=r"(r[3]) : "r"(addr));
}
__device__ __forceinline__ void mma16816(float* c, const uint32_t* a,
                                         uint32_t b0, uint32_t b1) {
    asm volatile(
        "mma.sync.aligned.m16n8k16.row.col.f32.f16.f16.f32 "
        "{%0,%1,%2,%3}, {%4,%5,%6,%7}, {%8,%9}, {%0,%1,%2,%3};"
        : "+f"(c[0]), "+f"(c[1]), "+f"(c[2]), "+f"(c[3])
        : "r"(a[0]), "r"(a[1]), "r"(a[2]), "r"(a[3]), "r"(b0), "r"(b1));
}

// ---------------------------------------------------------------------------
// 1-term GEMM: C = Ah @ Wh^T (fp16 in, fp32 accum). Two output flavors:
//  - fp16 C + amax(up half)/amax(gate half)/max_pos(gate) epilogue (fused)
//  - fp32 C, no epilogue (down, writes final output)
// 128x128 tile, 128 threads (4 warps, 64x64 warp tiles), 3-stage, 2 CTAs/SM.
// ---------------------------------------------------------------------------
#define TILE_BYTES 16384
#define NSTAGES 3
#define STAGE_BYTES (2 * TILE_BYTES)
#define GEMM_DYN_SMEM (NSTAGES * STAGE_BYTES + 1024)
#define GTHREADS 128

__device__ __forceinline__ void load_chunk(
    uint32_t sbase,
    const __half* __restrict__ Ah, const __half* __restrict__ Bh,
    int m0, int n0, int K, int k0, int tid)
{
    #pragma unroll
    for (int u = tid; u < 1024; u += GTHREADS) {
        int r = u >> 3, cc = u & 7;
        uint32_t off = (uint32_t)(r * 128 + cc * 16);
        uint32_t sw = off ^ ((off >> 3) & 0x70);
        size_t arow = (size_t)(m0 + r) * K + k0 + cc * 8;
        size_t brow = (size_t)(n0 + r) * K + k0 + cc * 8;
        cp16(sbase + sw,              Ah + arow);
        cp16(sbase + TILE_BYTES + sw, Bh + brow);
    }
}

// Shared mainloop body via macro-free duplication (simpler than templates here).
__device__ __forceinline__ void gemm_mainloop(
    const __half* __restrict__ Ah, const __half* __restrict__ Bh,
    int m0, int n0, int K, int tid, uint32_t dynbase,
    int m0w, int n0w, int rsel, int csel, float acc[4][8][4])
{
    const int NC = K >> 6;
    #pragma unroll
    for (int c = 0; c < NSTAGES; c++) {
        load_chunk(dynbase + c * STAGE_BYTES, Ah, Bh, m0, n0, K, c * 64, tid);
        asm volatile("cp.async.commit_group;" ::: "memory");
    }
    for (int c = 0; c < NC; ++c) {
        int s = c - (c / NSTAGES) * NSTAGES;
        asm volatile("cp.async.wait_group %0;" :: "n"(NSTAGES - 1) : "memory");
        __syncthreads();
        uint32_t sb = dynbase + s * STAGE_BYTES;
        uint32_t aH = sb, bH = sb + TILE_BYTES;

        #pragma unroll
        for (int ks = 0; ks < 4; ks++) {
            const int cb = ks * 32 + csel;
            uint32_t ah[4][4];
            #pragma unroll
            for (int mt = 0; mt < 4; mt++) {
                uint32_t off = (uint32_t)((m0w + mt * 16 + rsel) * 128 + cb);
                uint32_t sw = off ^ ((off >> 3) & 0x70);
                ldsm_x4(aH + sw, ah[mt]);
            }
            #pragma unroll
            for (int np = 0; np < 4; np++) {
                uint32_t off = (uint32_t)((n0w + np * 16 + rsel) * 128 + cb);
                uint32_t sw = off ^ ((off >> 3) & 0x70);
                uint32_t bh[4];
                ldsm_x4(bH + sw, bh);
                #pragma unroll
                for (int mt = 0; mt < 4; mt++) {
                    mma16816(acc[mt][np * 2 + 0], ah[mt], bh[0], bh[2]);
                    mma16816(acc[mt][np * 2 + 1], ah[mt], bh[1], bh[3]);
                }
            }
        }
        __syncthreads();
        if (c + NSTAGES < NC)
            load_chunk(dynbase + s * STAGE_BYTES, Ah, Bh, m0, n0, K,
                       (c + NSTAGES) * 64, tid);
        asm volatile("cp.async.commit_group;" ::: "memory");
    }
}

// fused up|gate GEMM: fp16 output + amax/maxpos epilogue
__global__ void __launch_bounds__(GTHREADS, 2)
gemm_ug(const __half* __restrict__ Ah, const __half* __restrict__ Bh,
        __half* __restrict__ C, int N, int K, unsigned int* amax)
{
    extern __shared__ char dynsmem[];
    __shared__ float s_red[8];
    const int tid = threadIdx.x;
    const int wid = tid >> 5;
    const int lid = tid & 31;
    const int m0 = blockIdx.y * 128;
    const int n0 = blockIdx.x * 128;
    uint32_t dynbase = smem_u32(dynsmem);
    dynbase = (dynbase + 1023u) & ~1023u;

    const int m0w = (wid & 1) * 64;
    const int n0w = (wid >> 1) * 64;
    float acc[4][8][4];
    #pragma unroll
    for (int i = 0; i < 4; i++)
        #pragma unroll
        for (int j = 0; j < 8; j++)
            #pragma unroll
            for (int q = 0; q < 4; q++) acc[i][j][q] = 0.0f;

    const int g  = lid >> 3;
    const int lr = lid & 7;
    const int rsel = (g & 1) * 8 + lr;
    const int csel = (g >> 1) * 16;

    gemm_mainloop(Ah, Bh, m0, n0, K, tid, dynbase, m0w, n0w, rsel, csel, acc);

    const int gq = lid >> 2, q4 = lid & 3;
    const bool is_gate = (n0 >= I_DIM);
    float lmax = 0.0f, lpos = 0.0f;
    #pragma unroll
    for (int mt = 0; mt < 4; mt++) {
        #pragma unroll
        for (int nt = 0; nt < 8; nt++) {
            __half* cp0 = C + (size_t)(m0 + m0w + mt * 16 + gq) * N
                            + n0 + n0w + nt * 8 + q4 * 2;
            __half* cp1 = cp0 + 8 * (size_t)N;
            *(__half2*)cp0 = __floats2half2_rn(acc[mt][nt][0], acc[mt][nt][1]);
            *(__half2*)cp1 = __floats2half2_rn(acc[mt][nt][2], acc[mt][nt][3]);
            #pragma unroll
            for (int q = 0; q < 4; q++) {
                lmax = fmaxf(lmax, fabsf(acc[mt][nt][q]));
                lpos = fmaxf(lpos, acc[mt][nt][q]);
            }
        }
    }
    #pragma unroll
    for (int o = 16; o; o >>= 1) {
        lmax = fmaxf(lmax, __shfl_xor_sync(0xffffffffu, lmax, o));
        lpos = fmaxf(lpos, __shfl_xor_sync(0xffffffffu, lpos, o));
    }
    if (lid == 0) { s_red[wid] = lmax; s_red[4 + wid] = lpos; }
    __syncthreads();
    if (tid == 0) {
        float m = s_red[0], p = s_red[4];
        #pragma unroll
        for (int i = 1; i < 4; i++) {
            m = fmaxf(m, s_red[i]);
            p = fmaxf(p, s_red[4 + i]);
        }
        atomicMax(&amax[is_gate ? 2 : 1], __float_as_uint(m));
        if (is_gate) atomicMax(&amax[5], __float_as_uint(fmaxf(p, 0.0f)));
    }
}

// down GEMM: fp32 output (final), no epilogue
__global__ void __launch_bounds__(GTHREADS, 2)
gemm_down(const __half* __restrict__ Ah, const __half* __restrict__ Bh,
          float* __restrict__ C, int N, int K)
{
    extern __shared__ char dynsmem[];
    const int tid = threadIdx.x;
    const int wid = tid >> 5;
    const int lid = tid & 31;
    const int m0 = blockIdx.y * 128;
    const int n0 = blockIdx.x * 128;
    uint32_t dynbase = smem_u32(dynsmem);
    dynbase = (dynbase + 1023u) & ~1023u;

    const int m0w = (wid & 1) * 64;
    const int n0w = (wid >> 1) * 64;
    float acc[4][8][4];
    #pragma unroll
    for (int i = 0; i < 4; i++)
        #pragma unroll
        for (int j = 0; j < 8; j++)
            #pragma unroll
            for (int q = 0; q < 4; q++) acc[i][j][q] = 0.0f;

    const int g  = lid >> 3;
    const int lr = lid & 7;
    const int rsel = (g & 1) * 8 + lr;
    const int csel = (g >> 1) * 16;

    gemm_mainloop(Ah, Bh, m0, n0, K, tid, dynbase, m0w, n0w, rsel, csel, acc);

    const int gq = lid >> 2, q4 = lid & 3;
    #pragma unroll
    for (int mt = 0; mt < 4; mt++) {
        #pragma unroll
        for (int nt = 0; nt < 8; nt++) {
            float* cp0 = C + (size_t)(m0 + m0w + mt * 16 + gq) * N
                           + n0 + n0w + nt * 8 + q4 * 2;
            float* cp1 = cp0 + 8 * (size_t)N;
            cp0[0] = acc[mt][nt][0]; cp0[1] = acc[mt][nt][1];
            cp1[0] = acc[mt][nt][2]; cp1[1] = acc[mt][nt][3];
        }
    }
}

// ---------------------------------------------------------------------------
// Elementwise
// ---------------------------------------------------------------------------
__global__ void k_zero_amax() {
    if (threadIdx.x < 8) g_amax[threadIdx.x] = 0u;
}

__global__ void k_amax(const float4* __restrict__ p, size_t n4, int slot) {
    float m = 0.0f;
    for (size_t i = (size_t)blockIdx.x * blockDim.x + threadIdx.x; i < n4;
         i += (size_t)gridDim.x * blockDim.x) {
        float4 v = p[i];
        m = fmaxf(m, fmaxf(fmaxf(fabsf(v.x), fabsf(v.y)),
                           fmaxf(fabsf(v.z), fabsf(v.w))));
    }
    #pragma unroll
    for (int o = 16; o; o >>= 1) m = fmaxf(m, __shfl_xor_sync(0xffffffffu, m, o));
    __shared__ float red[32];
    int wid = threadIdx.x >> 5, lid = threadIdx.x & 31;
    if (lid == 0) red[wid] = m;
    __syncthreads();
    if (threadIdx.x == 0) {
        int nw = (blockDim.x + 31) >> 5;
        float mm = red[0];
        for (int i = 1; i < nw; i++) mm = fmaxf(mm, red[i]);
        atomicMax(&g_amax[slot], __float_as_uint(mm));
    }
}

// qdq16 then single fp16 round
__global__ void k_quant_h(const float4* __restrict__ in,
                          __half2* __restrict__ h, size_t n4, int slot) {
    float s = scale16(__uint_as_float(g_amax[slot]));
    for (size_t i = (size_t)blockIdx.x * blockDim.x + threadIdx.x; i < n4;
         i += (size_t)gridDim.x * blockDim.x) {
        float4 v = in[i];
        h[2 * i]     = __floats2half2_rn(qdq16(v.x, s), qdq16(v.y, s));
        h[2 * i + 1] = __floats2half2_rn(qdq16(v.z, s), qdq16(v.w, s));
    }
}

__global__ void k_dequant_w(const float4* __restrict__ w,
                            __half2* __restrict__ oh, int n4) {
    int i = blockIdx.x * blockDim.x + threadIdx.x;
    if (i >= n4) return;
    float4 v = w[i];
    float r[4] = {v.x, v.y, v.z, v.w};
    float a = fmaxf(fmaxf(fabsf(r[0]), fabsf(r[1])),
                    fmaxf(fabsf(r[2]), fabsf(r[3])));
    #pragma unroll
    for (int o = 1; o < 8; o <<= 1)
        a = fmaxf(a, __shfl_xor_sync(0xffffffffu, a, o));
    float s = fmaxf(__fdiv_rn(a, 7.0f), 1e-12f);
    __half hh[4];
    #pragma unroll
    for (int c = 0; c < 4; c++) {
        float q = rintf(__fdiv_rn(r[c], s));
        q = fminf(fmaxf(q, -8.0f), 7.0f);
        hh[c] = __float2half_rn(q * s);
    }
    oh[2 * i]     = __halves2half2(hh[0], hh[1]);
    oh[2 * i + 1] = __halves2half2(hh[2], hh[3]);
}

// derive amax(t) from amax(gate) and max_pos(gate): t monotone for g>0,
// |t| <= 0.27847 on g<0 (negative-lobe ceiling).
__global__ void k_derive_t() {
    float sg = scale16(__uint_as_float(g_amax[2]));
    float mp = __uint_as_float(g_amax[5]);
    float t = silu_t(mp, sg);
    g_amax[3] = __float_as_uint(fmaxf(t, 0.27846822f));
}

// Interleaved fp16 layout: C[8192, 6144]; up cols [0,3072), gate [3072,6144)
#define ROW8  768      // float4(=8 half) units per row
#define HALF8 384      // per half-row

__device__ __forceinline__ void unpack8(float4 v, float* o) {
    const __half2* h = (const __half2*)&v;
    #pragma unroll
    for (int k = 0; k < 4; k++) {
        float2 f = __half22float2(h[k]);
        o[2 * k] = f.x; o[2 * k + 1] = f.y;
    }
}

__global__ void k_amax_p(const float4* __restrict__ C, size_t n8) {
    float sg = scale16(__uint_as_float(g_amax[2]));
    float st = scale16(__uint_as_float(g_amax[3]));
    float su = scale16(__uint_as_float(g_amax[1]));
    float m = 0.0f;
    for (size_t i = (size_t)blockIdx.x * blockDim.x + threadIdx.x; i < n8;
         i += (size_t)gridDim.x * blockDim.x) {
        size_t mm_ = i / HALF8, j = i - mm_ * HALF8;
        float ru[8], rg[8];
        unpack8(C[mm_ * ROW8 + j], ru);
        unpack8(C[mm_ * ROW8 + HALF8 + j], rg);
        #pragma unroll
        for (int c = 0; c < 8; c++) {
            float g2 = qdq16(silu_t(rg[c], sg), st);
            float u  = qdq16(ru[c], su);
            m = fmaxf(m, fabsf(g2 * u));
        }
    }
    #pragma unroll
    for (int o = 16; o; o >>= 1) m = fmaxf(m, __shfl_xor_sync(0xffffffffu, m, o));
    __shared__ float red[32];
    int wid = threadIdx.x >> 5, lid = threadIdx.x & 31;
    if (lid == 0) red[wid] = m;
    __syncthreads();
    if (threadIdx.x == 0) {
        int nw = (blockDim.x + 31) >> 5;
        float mm = red[0];
        for (int i = 1; i < nw; i++) mm = fmaxf(mm, red[i]);
        atomicMax(&g_amax[4], __float_as_uint(mm));
    }
}

__global__ void k_write_p(const float4* __restrict__ C,
                          __half2* __restrict__ ph, size_t n8) {
    float sg = scale16(__uint_as_float(g_amax[2]));
    float st = scale16(__uint_as_float(g_amax[3]));
    float su = scale16(__uint_as_float(g_amax[1]));
    float sp = scale16(__uint_as_float(g_amax[4]));
    for (size_t i = (size_t)blockIdx.x * blockDim.x + threadIdx.x; i < n8;
         i += (size_t)gridDim.x * blockDim.x) {
        size_t mm_ = i / HALF8, j = i - mm_ * HALF8;
        float ru[8], rg[8];
        unpack8(C[mm_ * ROW8 + j], ru);
        unpack8(C[mm_ * ROW8 + HALF8 + j], rg);
        __half hh[8];
        #pragma unroll
        for (int c = 0; c < 8; c++) {
            float g2 = qdq16(silu_t(rg[c], sg), st);
            float u  = qdq16(ru[c], su);
            hh[c] = __float2half_rn(qdq16(g2 * u, sp));
        }
        #pragma unroll
        for (int k = 0; k < 4; k++)
            ph[4 * i + k] = __halves2half2(hh[2 * k], hh[2 * k + 1]);
    }
}

// ---------------------------------------------------------------------------
// Host launch
// ---------------------------------------------------------------------------
extern "C" void kernel_launch(void* const* d_in, const int* in_sizes, int n_in,
                              void* d_out, int out_size)
{
    const float* x  = (const float*)d_in[0];
    const float* wg = (const float*)d_in[1];
    const float* wu = (const float*)d_in[2];
    const float* wd = (const float*)d_in[3];
    float* out = (float*)d_out;

    __half *p_xh, *p_wug, *p_wd, *p_ph, *p_ug;
    unsigned int* p_amax;
    cudaGetSymbolAddress((void**)&p_xh,  g_xh);
    cudaGetSymbolAddress((void**)&p_wug, g_wug);
    cudaGetSymbolAddress((void**)&p_wd,  g_wd);
    cudaGetSymbolAddress((void**)&p_ph,  g_ph);
    cudaGetSymbolAddress((void**)&p_ug,  g_ug);
    cudaGetSymbolAddress((void**)&p_amax, g_amax);

    cudaFuncSetAttribute(gemm_ug,
                         cudaFuncAttributeMaxDynamicSharedMemorySize, GEMM_DYN_SMEM);
    cudaFuncSetAttribute(gemm_down,
                         cudaFuncAttributeMaxDynamicSharedMemorySize, GEMM_DYN_SMEM);

    const size_t nx4 = (size_t)M_TOK * H_DIM / 4;
    const size_t ni8 = (size_t)M_TOK * I_DIM / 8;   // 8-half units per half
    const int nw4 = (I_DIM * H_DIM) / 4;

    k_zero_amax<<<1, 8>>>();
    k_amax<<<2048, 256>>>((const float4*)x, nx4, 0);
    k_quant_h<<<2048, 256>>>((const float4*)x, (__half2*)p_xh, nx4, 0);
    k_dequant_w<<<nw4 / 256, 256>>>((const float4*)wu, (__half2*)p_wug, nw4);
    k_dequant_w<<<nw4 / 256, 256>>>((const float4*)wg,
                                    (__half2*)(p_wug + (size_t)I_DIM * H_DIM), nw4);

    // fused up|gate GEMM -> fp16 C[8192, 6144] + amax/maxpos epilogue
    {
        dim3 grid(NI2 / 128, M_TOK / 128);     // (48, 64)
        gemm_ug<<<grid, GTHREADS, GEMM_DYN_SMEM>>>(
            p_xh, p_wug, p_ug, NI2, H_DIM, p_amax);
    }
    k_dequant_w<<<nw4 / 256, 256>>>((const float4*)wd, (__half2*)p_wd, nw4);

    // derive amax(t) analytically (no 100MB pass)
    k_derive_t<<<1, 1>>>();

    // amax(p) + write ph (fp16 reads)
    k_amax_p<<<4096, 256>>>((const float4*)p_ug, ni8);
    k_write_p<<<4096, 256>>>((const float4*)p_ug, (__half2*)p_ph, ni8);

    // down GEMM (single term) -> fp32 out
    {
        dim3 grid(H_DIM / 128, M_TOK / 128);   // (8, 64)
        gemm_down<<<grid, GTHREADS, GEMM_DYN_SMEM>>>(
            p_ph, p_wd, out, H_DIM, I_DIM);
    }
}